// round 5
// baseline (speedup 1.0000x reference)
#include <cuda_runtime.h>
#include <math.h>

#define N_NODES 50000
#define N_EDGES 800000
#define L_IN    1024
#define D_HID   256
#define HTOT    (N_NODES * D_HID)

// ---------------- scratch (device globals; no allocation allowed) ----------------
__device__ float g_Z[(size_t)N_NODES * 1024];   // [q | k | v | s] per node, 1024 cols
__device__ float g_W1[(size_t)L_IN * 1024];     // packed [Wq|Wk|Wv|Ws]
__device__ float g_b1[1024];
__device__ float g_T[(size_t)N_NODES * 512];    // [h@Wa+ba | h@Wb+bb]
__device__ float g_W2[(size_t)D_HID * 512];     // packed [Wa|Wb]
__device__ float g_b2[512];
__device__ float g_ex[N_EDGES];
__device__ float g_den[N_NODES];
__device__ float g_msg[(size_t)N_NODES * D_HID];
__device__ float g_scores[N_NODES * 2];
__device__ unsigned g_smax[2];
__device__ float g_ssum[2];

// monotone float<->uint map for atomicMax on signed floats
__device__ __forceinline__ unsigned fmapU(float f) {
    int i = __float_as_int(f);
    return (i < 0) ? ~((unsigned)i) : (((unsigned)i) | 0x80000000u);
}
__device__ __forceinline__ float funmapU(unsigned u) {
    int i = (u & 0x80000000u) ? (int)(u & 0x7fffffffu) : (int)(~u);
    return __int_as_float(i);
}

// ---------------- pack kernels ----------------
__global__ void pack1_kernel(const float* __restrict__ Wq, const float* __restrict__ Wk,
                             const float* __restrict__ Wv, const float* __restrict__ Ws,
                             const float* __restrict__ bq, const float* __restrict__ bk,
                             const float* __restrict__ bv, const float* __restrict__ bs) {
    int i = blockIdx.x * blockDim.x + threadIdx.x;
    if (i < L_IN * 1024) {
        int k = i >> 10, c = i & 1023;
        int m = c >> 8, lc = c & 255;
        const float* W = (m == 0) ? Wq : (m == 1) ? Wk : (m == 2) ? Wv : Ws;
        g_W1[i] = W[k * 256 + lc];
    }
    if (i < 1024) {
        int m = i >> 8, lc = i & 255;
        const float* b = (m == 0) ? bq : (m == 1) ? bk : (m == 2) ? bv : bs;
        g_b1[i] = b[lc];
    }
}

__global__ void pack2_kernel(const float* __restrict__ Wa, const float* __restrict__ Wb,
                             const float* __restrict__ ba, const float* __restrict__ bb) {
    int i = blockIdx.x * blockDim.x + threadIdx.x;
    if (i < D_HID * 512) {
        int k = i >> 9, c = i & 511;
        int m = c >> 8, lc = c & 255;
        const float* W = (m == 0) ? Wa : Wb;
        g_W2[i] = W[k * 256 + lc];
    }
    if (i < 512) {
        int m = i >> 8, lc = i & 255;
        g_b2[i] = (m == 0) ? ba[lc] : bb[lc];
    }
}

// ---------------- init ----------------
__global__ void init_kernel(float* __restrict__ y) {
    int i = blockIdx.x * blockDim.x + threadIdx.x;
    int stride = gridDim.x * blockDim.x;
    for (int j = i; j < HTOT; j += stride) g_msg[j] = 0.f;
    for (int j = i; j < N_NODES; j += stride) g_den[j] = 0.f;
    if (i < 512) y[i] = 0.f;
    if (i < 2) { g_ssum[i] = 0.f; g_smax[i] = 0u; }
}

// ---------------- SGEMM: C[M,N] = A[M,K] @ B[K,N] + bias[N] ----------------
#define BM 128
#define BN 64
#define BKK 16
__global__ __launch_bounds__(256) void sgemm_bias(
    const float* __restrict__ A, const float* __restrict__ B,
    const float* __restrict__ bias, float* __restrict__ C,
    int M, int N, int K)
{
    __shared__ float As[BKK][BM + 4];
    __shared__ float Bs[BKK][BN + 4];
    int n0 = blockIdx.x * BN;
    int m0 = blockIdx.y * BM;
    int tid = threadIdx.x;
    int tx = tid & 15;      // column group 0..15 (4 cols each)
    int ty = tid >> 4;      // row group 0..15 (8 rows each)

    float acc[8][4];
    #pragma unroll
    for (int i = 0; i < 8; i++)
        #pragma unroll
        for (int j = 0; j < 4; j++) acc[i][j] = 0.f;

    int arow0 = tid >> 2;            // 0..63
    int akq   = (tid & 3) * 4;       // 0,4,8,12
    int brow  = tid >> 4;            // 0..15
    int bcol  = (tid & 15) * 4;      // 0..60

    for (int kk = 0; kk < K; kk += BKK) {
        #pragma unroll
        for (int half = 0; half < 2; half++) {
            int row = arow0 + half * 64;
            int gm = m0 + row;
            float4 av = make_float4(0.f, 0.f, 0.f, 0.f);
            if (gm < M) av = *(const float4*)&A[(size_t)gm * K + kk + akq];
            As[akq + 0][row] = av.x;
            As[akq + 1][row] = av.y;
            As[akq + 2][row] = av.z;
            As[akq + 3][row] = av.w;
        }
        {
            float4 bv = *(const float4*)&B[(size_t)(kk + brow) * N + n0 + bcol];
            Bs[brow][bcol + 0] = bv.x;
            Bs[brow][bcol + 1] = bv.y;
            Bs[brow][bcol + 2] = bv.z;
            Bs[brow][bcol + 3] = bv.w;
        }
        __syncthreads();
        #pragma unroll
        for (int k = 0; k < BKK; k++) {
            float a[8], b[4];
            #pragma unroll
            for (int i = 0; i < 8; i++) a[i] = As[k][ty * 8 + i];
            #pragma unroll
            for (int j = 0; j < 4; j++) b[j] = Bs[k][tx * 4 + j];
            #pragma unroll
            for (int i = 0; i < 8; i++)
                #pragma unroll
                for (int j = 0; j < 4; j++)
                    acc[i][j] += a[i] * b[j];
        }
        __syncthreads();
    }

    float b0 = bias[n0 + tx * 4 + 0];
    float b1 = bias[n0 + tx * 4 + 1];
    float b2 = bias[n0 + tx * 4 + 2];
    float b3 = bias[n0 + tx * 4 + 3];
    #pragma unroll
    for (int i = 0; i < 8; i++) {
        int gm = m0 + ty * 8 + i;
        if (gm < M) {
            float4 o;
            o.x = acc[i][0] + b0;
            o.y = acc[i][1] + b1;
            o.z = acc[i][2] + b2;
            o.w = acc[i][3] + b3;
            *(float4*)&C[(size_t)gm * N + n0 + tx * 4] = o;
        }
    }
}

// ---------------- edge kernels ----------------
// one warp per edge: ex = exp(dot(q[dst], k[src]) / 16); den[dst] += ex
__global__ void edge_alpha_kernel(const int* __restrict__ ei) {
    int warp = (blockIdx.x * blockDim.x + threadIdx.x) >> 5;
    int lane = threadIdx.x & 31;
    if (warp >= N_EDGES) return;
    int src = ei[warp];
    int dst = ei[N_EDGES + warp];
    const float* q = g_Z + (size_t)dst * 1024;         // q cols 0..255
    const float* k = g_Z + (size_t)src * 1024 + 256;   // k cols 256..511
    float4 qa = *(const float4*)&q[lane * 4];
    float4 qb = *(const float4*)&q[128 + lane * 4];
    float4 ka = *(const float4*)&k[lane * 4];
    float4 kb = *(const float4*)&k[128 + lane * 4];
    float s = qa.x * ka.x + qa.y * ka.y + qa.z * ka.z + qa.w * ka.w
            + qb.x * kb.x + qb.y * kb.y + qb.z * kb.z + qb.w * kb.w;
    #pragma unroll
    for (int o = 16; o > 0; o >>= 1) s += __shfl_down_sync(0xffffffffu, s, o);
    if (lane == 0) {
        float ex = expf(s * 0.0625f);   // alpha - max is skipped: mathematically identical
        g_ex[warp] = ex;
        atomicAdd(&g_den[dst], ex);
    }
}

// one warp per edge: msg[dst] += (ex/(den[dst]+1e-16)) * v[src]
__global__ void edge_scatter_kernel(const int* __restrict__ ei) {
    int warp = (blockIdx.x * blockDim.x + threadIdx.x) >> 5;
    int lane = threadIdx.x & 31;
    if (warp >= N_EDGES) return;
    int src = ei[warp];
    int dst = ei[N_EDGES + warp];
    float w = g_ex[warp] / (g_den[dst] + 1e-16f);
    const float* v = g_Z + (size_t)src * 1024 + 512;   // v cols 512..767
    float* o = g_msg + (size_t)dst * 256;
    float4 va = *(const float4*)&v[lane * 4];
    float4 vb = *(const float4*)&v[128 + lane * 4];
    atomicAdd(&o[lane * 4 + 0],       w * va.x);
    atomicAdd(&o[lane * 4 + 1],       w * va.y);
    atomicAdd(&o[lane * 4 + 2],       w * va.z);
    atomicAdd(&o[lane * 4 + 3],       w * va.w);
    atomicAdd(&o[128 + lane * 4 + 0], w * vb.x);
    atomicAdd(&o[128 + lane * 4 + 1], w * vb.y);
    atomicAdd(&o[128 + lane * 4 + 2], w * vb.z);
    atomicAdd(&o[128 + lane * 4 + 3], w * vb.w);
}

// ---------------- h = gelu(msg + s), written into d_out's h slice ----------------
__global__ void gelu_kernel(float* __restrict__ hout) {
    int i = blockIdx.x * blockDim.x + threadIdx.x;
    if (i >= HTOT) return;
    int n = i >> 8, c = i & 255;
    float xv = g_msg[i] + g_Z[(size_t)n * 1024 + 768 + c];  // s cols 768..1023
    float hv = 0.5f * xv * (1.0f + erff(xv * 0.70710678118654752f));
    hout[i] = hv;
}

// ---------------- scores: g = tanh(t1)*sigmoid(t2); scores = g @ Wc + bc ----------------
__global__ void scores_kernel(const float* __restrict__ Wc, const float* __restrict__ bc) {
    int warp = (blockIdx.x * blockDim.x + threadIdx.x) >> 5;
    int lane = threadIdx.x & 31;
    if (warp >= N_NODES) return;
    const float* t = g_T + (size_t)warp * 512;
    float acc0 = 0.f, acc1 = 0.f;
    #pragma unroll
    for (int half = 0; half < 2; half++) {
        int c0 = half * 128 + lane * 4;
        float4 t1 = *(const float4*)&t[c0];
        float4 t2 = *(const float4*)&t[256 + c0];
        float g0 = tanhf(t1.x) * (1.f / (1.f + expf(-t2.x)));
        float g1 = tanhf(t1.y) * (1.f / (1.f + expf(-t2.y)));
        float g2 = tanhf(t1.z) * (1.f / (1.f + expf(-t2.z)));
        float g3 = tanhf(t1.w) * (1.f / (1.f + expf(-t2.w)));
        acc0 += g0 * Wc[(c0 + 0) * 2] + g1 * Wc[(c0 + 1) * 2] + g2 * Wc[(c0 + 2) * 2] + g3 * Wc[(c0 + 3) * 2];
        acc1 += g0 * Wc[(c0 + 0) * 2 + 1] + g1 * Wc[(c0 + 1) * 2 + 1] + g2 * Wc[(c0 + 2) * 2 + 1] + g3 * Wc[(c0 + 3) * 2 + 1];
    }
    #pragma unroll
    for (int o = 16; o > 0; o >>= 1) {
        acc0 += __shfl_down_sync(0xffffffffu, acc0, o);
        acc1 += __shfl_down_sync(0xffffffffu, acc1, o);
    }
    if (lane == 0) {
        float s0 = acc0 + bc[0];
        float s1 = acc1 + bc[1];
        g_scores[2 * warp]     = s0;
        g_scores[2 * warp + 1] = s1;
        atomicMax(&g_smax[0], fmapU(s0));
        atomicMax(&g_smax[1], fmapU(s1));
    }
}

// ---------------- softmax denominators over all nodes ----------------
__global__ void sumexp_kernel() {
    float m0 = funmapU(g_smax[0]);
    float m1 = funmapU(g_smax[1]);
    int i = blockIdx.x * blockDim.x + threadIdx.x;
    int stride = gridDim.x * blockDim.x;
    float e0 = 0.f, e1 = 0.f;
    for (int n = i; n < N_NODES; n += stride) {
        e0 += expf(g_scores[2 * n]     - m0);
        e1 += expf(g_scores[2 * n + 1] - m1);
    }
    #pragma unroll
    for (int o = 16; o > 0; o >>= 1) {
        e0 += __shfl_down_sync(0xffffffffu, e0, o);
        e1 += __shfl_down_sync(0xffffffffu, e1, o);
    }
    if ((threadIdx.x & 31) == 0) {
        atomicAdd(&g_ssum[0], e0);
        atomicAdd(&g_ssum[1], e1);
    }
}

// ---------------- finalize: A = attn[:,label]; y = attn^T @ h ----------------
#define CHUNK 128
__global__ __launch_bounds__(256) void finalize_kernel(
    const float* __restrict__ h, const int* __restrict__ label,
    float* __restrict__ y, float* __restrict__ A)
{
    __shared__ float sA0[CHUNK], sA1[CHUNK];
    float m0 = funmapU(g_smax[0]);
    float m1 = funmapU(g_smax[1]);
    float inv0 = 1.f / g_ssum[0];
    float inv1 = 1.f / g_ssum[1];
    int base = blockIdx.x * CHUNK;
    int t = threadIdx.x;
    int lab = label ? *label : 1;
    if (t < CHUNK) {
        int n = base + t;
        if (n < N_NODES) {
            float a0 = expf(g_scores[2 * n]     - m0) * inv0;
            float a1 = expf(g_scores[2 * n + 1] - m1) * inv1;
            sA0[t] = a0;
            sA1[t] = a1;
            A[n] = lab ? a1 : a0;
        } else {
            sA0[t] = 0.f;
            sA1[t] = 0.f;
        }
    }
    __syncthreads();
    float y0 = 0.f, y1 = 0.f;
    int nmax = N_NODES - base;
    if (nmax > CHUNK) nmax = CHUNK;
    for (int j = 0; j < nmax; j++) {
        float hv = h[(size_t)(base + j) * 256 + t];
        y0 += sA0[j] * hv;
        y1 += sA1[j] * hv;
    }
    atomicAdd(&y[t],       y0);
    atomicAdd(&y[256 + t], y1);
}

// ---------------- launch ----------------
extern "C" void kernel_launch(void* const* d_in, const int* in_sizes, int n_in,
                              void* d_out, int out_size)
{
    const float* x  = (const float*)d_in[0];
    const float* Wq = (const float*)d_in[1];
    const float* bq = (const float*)d_in[2];
    const float* Wk = (const float*)d_in[3];
    const float* bk = (const float*)d_in[4];
    const float* Wv = (const float*)d_in[5];
    const float* bv = (const float*)d_in[6];
    const float* Ws = (const float*)d_in[7];
    const float* bs = (const float*)d_in[8];
    const float* Wa = (const float*)d_in[9];
    const float* ba = (const float*)d_in[10];
    const float* Wb = (const float*)d_in[11];
    const float* bb = (const float*)d_in[12];
    const float* Wc = (const float*)d_in[13];
    const float* bc = (const float*)d_in[14];
    const int*   ei = (const int*)d_in[15];
    const int*   lab = (n_in > 16) ? (const int*)d_in[16] : nullptr;

    float* out = (float*)d_out;
    float* y = out;                       // [2, 256]
    float* A = out + 512;                 // [50000]
    float* h = out + 512 + N_NODES;       // [50000, 256]

    float *pZ, *pW1, *pb1, *pT, *pW2, *pb2;
    cudaGetSymbolAddress((void**)&pZ,  g_Z);
    cudaGetSymbolAddress((void**)&pW1, g_W1);
    cudaGetSymbolAddress((void**)&pb1, g_b1);
    cudaGetSymbolAddress((void**)&pT,  g_T);
    cudaGetSymbolAddress((void**)&pW2, g_W2);
    cudaGetSymbolAddress((void**)&pb2, g_b2);

    pack1_kernel<<<(L_IN * 1024 + 255) / 256, 256>>>(Wq, Wk, Wv, Ws, bq, bk, bv, bs);
    pack2_kernel<<<(D_HID * 512 + 255) / 256, 256>>>(Wa, Wb, ba, bb);
    init_kernel<<<4096, 256>>>(y);

    // Z = x @ [Wq|Wk|Wv|Ws] + bias   (M=50000, N=1024, K=1024)
    sgemm_bias<<<dim3(1024 / BN, (N_NODES + BM - 1) / BM), 256>>>(
        x, pW1, pb1, pZ, N_NODES, 1024, 1024);

    edge_alpha_kernel<<<(N_EDGES * 32 + 255) / 256, 256>>>(ei);
    edge_scatter_kernel<<<(N_EDGES * 32 + 255) / 256, 256>>>(ei);

    gelu_kernel<<<(HTOT + 255) / 256, 256>>>(h);

    // T = h @ [Wa|Wb] + bias   (M=50000, N=512, K=256)
    sgemm_bias<<<dim3(512 / BN, (N_NODES + BM - 1) / BM), 256>>>(
        h, pW2, pb2, pT, N_NODES, 512, 256);

    scores_kernel<<<(N_NODES * 32 + 255) / 256, 256>>>(Wc, bc);
    sumexp_kernel<<<256, 256>>>();
    finalize_kernel<<<(N_NODES + CHUNK - 1) / CHUNK, 256>>>(h, lab, y, A);
}

// round 6
// speedup vs baseline: 1.2949x; 1.2949x over previous
#include <cuda_runtime.h>
#include <mma.h>
#include <math.h>

using namespace nvcuda;

#define N_NODES 50000
#define N_EDGES 800000
#define L_IN    1024
#define D_HID   256
#define HTOT    (N_NODES * D_HID)

// ---------------- scratch (device globals; no allocation allowed) ----------------
__device__ float g_Z[(size_t)N_NODES * 1024];   // [q | k | v | s] per node, 1024 cols
__device__ float g_W1[(size_t)L_IN * 1024];     // packed [Wq|Wk|Wv|Ws]
__device__ float g_b1[1024];
__device__ float g_T[(size_t)N_NODES * 512];    // [h@Wa+ba | h@Wb+bb]
__device__ float g_W2[(size_t)D_HID * 512];     // packed [Wa|Wb]
__device__ float g_b2[512];
__device__ float g_ex[N_EDGES];
__device__ float g_scores[N_NODES * 2];
__device__ unsigned g_smax[2];
__device__ float g_ssum[2];
// CSR scratch
__device__ int g_cnt[N_NODES];
__device__ int g_off[N_NODES];
__device__ int g_cur[N_NODES];
__device__ int g_eid[N_EDGES];
__device__ int g_srcs[N_EDGES];

// monotone float<->uint map for atomicMax on signed floats
__device__ __forceinline__ unsigned fmapU(float f) {
    int i = __float_as_int(f);
    return (i < 0) ? ~((unsigned)i) : (((unsigned)i) | 0x80000000u);
}
__device__ __forceinline__ float funmapU(unsigned u) {
    int i = (u & 0x80000000u) ? (int)(u & 0x7fffffffu) : (int)(~u);
    return __int_as_float(i);
}

// ---------------- pack kernels ----------------
__global__ void pack1_kernel(const float* __restrict__ Wq, const float* __restrict__ Wk,
                             const float* __restrict__ Wv, const float* __restrict__ Ws,
                             const float* __restrict__ bq, const float* __restrict__ bk,
                             const float* __restrict__ bv, const float* __restrict__ bs) {
    int i = blockIdx.x * blockDim.x + threadIdx.x;
    if (i < L_IN * 1024) {
        int k = i >> 10, c = i & 1023;
        int m = c >> 8, lc = c & 255;
        const float* W = (m == 0) ? Wq : (m == 1) ? Wk : (m == 2) ? Wv : Ws;
        g_W1[i] = W[k * 256 + lc];
    }
    if (i < 1024) {
        int m = i >> 8, lc = i & 255;
        const float* b = (m == 0) ? bq : (m == 1) ? bk : (m == 2) ? bv : bs;
        g_b1[i] = b[lc];
    }
}

__global__ void pack2_kernel(const float* __restrict__ Wa, const float* __restrict__ Wb,
                             const float* __restrict__ ba, const float* __restrict__ bb) {
    int i = blockIdx.x * blockDim.x + threadIdx.x;
    if (i < D_HID * 512) {
        int k = i >> 9, c = i & 511;
        int m = c >> 8, lc = c & 255;
        const float* W = (m == 0) ? Wa : Wb;
        g_W2[i] = W[k * 256 + lc];
    }
    if (i < 512) {
        int m = i >> 8, lc = i & 255;
        g_b2[i] = (m == 0) ? ba[lc] : bb[lc];
    }
}

// ---------------- init ----------------
__global__ void init_kernel(float* __restrict__ y) {
    int i = blockIdx.x * blockDim.x + threadIdx.x;
    int stride = gridDim.x * blockDim.x;
    for (int j = i; j < N_NODES; j += stride) g_cnt[j] = 0;
    if (i < 512) y[i] = 0.f;
    if (i < 2) { g_ssum[i] = 0.f; g_smax[i] = 0u; }
}

// ---------------- TF32 tensor-core GEMM: C[M,N] = A[M,K] @ B[K,N] + bias[N] ----------------
// BM=128, BN=64, BK=32, 256 threads = 8 warps (4 along M x 2 along N),
// each warp computes 32x32 via 2x2 wmma m16n16k8 tf32 fragments.
#define BM 128
#define BN 64
#define BK 32

union SmemU {
    struct { float As[BK][BM + 4]; float Bs[BK][BN + 4]; } ab;  // As: k-major (col_major frags)
    float Cs[BM][BN + 4];
};

__global__ __launch_bounds__(256) void gemm_tf32_bias(
    const float* __restrict__ A, const float* __restrict__ B,
    const float* __restrict__ bias, float* __restrict__ C,
    int M, int N, int K)
{
    __shared__ SmemU sm;
    int n0 = blockIdx.x * BN;
    int m0 = blockIdx.y * BM;
    int tid = threadIdx.x;
    int warpId = tid >> 5;
    int warp_m = warpId & 3;          // 0..3  -> 32 rows each
    int warp_n = warpId >> 2;         // 0..1  -> 32 cols each
    int wm0 = warp_m * 32;
    int wn0 = warp_n * 32;

    // global->shared mapping
    int arow = tid >> 1;              // 0..127
    int ak0  = (tid & 1) * 16;        // 0 or 16
    int brow = tid >> 3;              // 0..31
    int bc0  = (tid & 7) * 8;         // 0..56

    wmma::fragment<wmma::accumulator, 16, 16, 8, float> acc[2][2];
    #pragma unroll
    for (int i = 0; i < 2; i++)
        #pragma unroll
        for (int j = 0; j < 2; j++)
            wmma::fill_fragment(acc[i][j], 0.0f);

    int gm_a = m0 + arow;
    bool a_ok = (gm_a < M);
    const float* Arow = A + (size_t)gm_a * K;

    for (int kk = 0; kk < K; kk += BK) {
        // load A tile (128 x 32), store transposed As[k][m]
        #pragma unroll
        for (int i = 0; i < 4; i++) {
            int kq = ak0 + i * 4;
            float4 av = make_float4(0.f, 0.f, 0.f, 0.f);
            if (a_ok) av = *(const float4*)&Arow[kk + kq];
            sm.ab.As[kq + 0][arow] = av.x;
            sm.ab.As[kq + 1][arow] = av.y;
            sm.ab.As[kq + 2][arow] = av.z;
            sm.ab.As[kq + 3][arow] = av.w;
        }
        // load B tile (32 x 64)
        #pragma unroll
        for (int i = 0; i < 2; i++) {
            int c = bc0 + i * 4;
            float4 bv = *(const float4*)&B[(size_t)(kk + brow) * N + n0 + c];
            sm.ab.Bs[brow][c + 0] = bv.x;
            sm.ab.Bs[brow][c + 1] = bv.y;
            sm.ab.Bs[brow][c + 2] = bv.z;
            sm.ab.Bs[brow][c + 3] = bv.w;
        }
        __syncthreads();

        #pragma unroll
        for (int ks = 0; ks < BK; ks += 8) {
            wmma::fragment<wmma::matrix_a, 16, 16, 8, wmma::precision::tf32, wmma::col_major> a0, a1;
            wmma::fragment<wmma::matrix_b, 16, 16, 8, wmma::precision::tf32, wmma::row_major> b0, b1;
            wmma::load_matrix_sync(a0, &sm.ab.As[ks][wm0],      BM + 4);
            wmma::load_matrix_sync(a1, &sm.ab.As[ks][wm0 + 16], BM + 4);
            wmma::load_matrix_sync(b0, &sm.ab.Bs[ks][wn0],      BN + 4);
            wmma::load_matrix_sync(b1, &sm.ab.Bs[ks][wn0 + 16], BN + 4);
            #pragma unroll
            for (int t = 0; t < a0.num_elements; t++) {
                a0.x[t] = wmma::__float_to_tf32(a0.x[t]);
                a1.x[t] = wmma::__float_to_tf32(a1.x[t]);
            }
            #pragma unroll
            for (int t = 0; t < b0.num_elements; t++) {
                b0.x[t] = wmma::__float_to_tf32(b0.x[t]);
                b1.x[t] = wmma::__float_to_tf32(b1.x[t]);
            }
            wmma::mma_sync(acc[0][0], a0, b0, acc[0][0]);
            wmma::mma_sync(acc[0][1], a0, b1, acc[0][1]);
            wmma::mma_sync(acc[1][0], a1, b0, acc[1][0]);
            wmma::mma_sync(acc[1][1], a1, b1, acc[1][1]);
        }
        __syncthreads();
    }

    // stage accumulators through shared, add bias, write out
    #pragma unroll
    for (int i = 0; i < 2; i++)
        #pragma unroll
        for (int j = 0; j < 2; j++)
            wmma::store_matrix_sync(&sm.Cs[wm0 + i * 16][wn0 + j * 16], acc[i][j],
                                    BN + 4, wmma::mem_row_major);
    __syncthreads();

    int rr = tid >> 4;          // 0..15
    int cc = (tid & 15) * 4;    // 0..60
    float4 bv = *(const float4*)&bias[n0 + cc];
    #pragma unroll
    for (int chunk = 0; chunk < 8; chunk++) {
        int row = chunk * 16 + rr;
        int gm = m0 + row;
        if (gm < M) {
            float4 o;
            o.x = sm.Cs[row][cc + 0] + bv.x;
            o.y = sm.Cs[row][cc + 1] + bv.y;
            o.z = sm.Cs[row][cc + 2] + bv.z;
            o.w = sm.Cs[row][cc + 3] + bv.w;
            *(float4*)&C[(size_t)gm * N + n0 + cc] = o;
        }
    }
}

// ---------------- CSR build ----------------
__global__ void count_kernel(const int* __restrict__ ei) {
    int i = blockIdx.x * blockDim.x + threadIdx.x;
    if (i < N_EDGES) atomicAdd(&g_cnt[ei[N_EDGES + i]], 1);
}

__global__ __launch_bounds__(1024) void scan_kernel() {
    __shared__ int part[1024];
    const int CH = (N_NODES + 1023) / 1024;   // 49
    int t = threadIdx.x;
    int base = t * CH;
    int s = 0;
    for (int j = 0; j < CH; j++) {
        int idx = base + j;
        if (idx < N_NODES) s += g_cnt[idx];
    }
    part[t] = s;
    __syncthreads();
    for (int off = 1; off < 1024; off <<= 1) {
        int v = (t >= off) ? part[t - off] : 0;
        __syncthreads();
        part[t] += v;
        __syncthreads();
    }
    int run = part[t] - s;   // exclusive prefix
    for (int j = 0; j < CH; j++) {
        int idx = base + j;
        if (idx < N_NODES) {
            g_off[idx] = run;
            g_cur[idx] = run;
            run += g_cnt[idx];
        }
    }
}

__global__ void fill_kernel(const int* __restrict__ ei) {
    int i = blockIdx.x * blockDim.x + threadIdx.x;
    if (i >= N_EDGES) return;
    int src = ei[i];
    int dst = ei[N_EDGES + i];
    int pos = atomicAdd(&g_cur[dst], 1);
    g_eid[pos] = i;
    g_srcs[pos] = src;
}

// ---------------- edge alpha: ex = exp(dot(q[dst], k[src]) / 16) ----------------
__global__ void edge_alpha_kernel(const int* __restrict__ ei) {
    int warp = (blockIdx.x * blockDim.x + threadIdx.x) >> 5;
    int lane = threadIdx.x & 31;
    if (warp >= N_EDGES) return;
    int src = ei[warp];
    int dst = ei[N_EDGES + warp];
    const float* q = g_Z + (size_t)dst * 1024;         // q cols 0..255
    const float* k = g_Z + (size_t)src * 1024 + 256;   // k cols 256..511
    float4 qa = *(const float4*)&q[lane * 4];
    float4 qb = *(const float4*)&q[128 + lane * 4];
    float4 ka = *(const float4*)&k[lane * 4];
    float4 kb = *(const float4*)&k[128 + lane * 4];
    float s = qa.x * ka.x + qa.y * ka.y + qa.z * ka.z + qa.w * ka.w
            + qb.x * kb.x + qb.y * kb.y + qb.z * kb.z + qb.w * kb.w;
    #pragma unroll
    for (int o = 16; o > 0; o >>= 1) s += __shfl_down_sync(0xffffffffu, s, o);
    if (lane == 0) g_ex[warp] = expf(s * 0.0625f);  // softmax max-shift skipped: identical
}

// ---------------- gather: per-node den + weighted sum of v[src], fused gelu ----------------
__global__ void gather_kernel(float* __restrict__ hout) {
    int warp = (blockIdx.x * blockDim.x + threadIdx.x) >> 5;
    int lane = threadIdx.x & 31;
    if (warp >= N_NODES) return;
    int start = g_off[warp];
    int deg = g_cnt[warp];

    float den = 0.f;
    for (int i = lane; i < deg; i += 32) den += g_ex[g_eid[start + i]];
    #pragma unroll
    for (int o = 16; o > 0; o >>= 1) den += __shfl_xor_sync(0xffffffffu, den, o);
    float inv = 1.f / (den + 1e-16f);

    float4 accA = make_float4(0.f, 0.f, 0.f, 0.f);
    float4 accB = make_float4(0.f, 0.f, 0.f, 0.f);
    for (int i = 0; i < deg; i++) {
        int p = start + i;
        float w = g_ex[g_eid[p]] * inv;
        const float* v = g_Z + (size_t)g_srcs[p] * 1024 + 512;   // v cols 512..767
        float4 va = *(const float4*)&v[lane * 4];
        float4 vb = *(const float4*)&v[128 + lane * 4];
        accA.x += w * va.x; accA.y += w * va.y; accA.z += w * va.z; accA.w += w * va.w;
        accB.x += w * vb.x; accB.y += w * vb.y; accB.z += w * vb.z; accB.w += w * vb.w;
    }

    // h = gelu(msg + s)
    const float* sp = g_Z + (size_t)warp * 1024 + 768;   // s cols 768..1023
    float4 sa = *(const float4*)&sp[lane * 4];
    float4 sb = *(const float4*)&sp[128 + lane * 4];
    float4 ha, hb;
    {
        float v0 = accA.x + sa.x, v1 = accA.y + sa.y, v2 = accA.z + sa.z, v3 = accA.w + sa.w;
        ha.x = 0.5f * v0 * (1.0f + erff(v0 * 0.70710678118654752f));
        ha.y = 0.5f * v1 * (1.0f + erff(v1 * 0.70710678118654752f));
        ha.z = 0.5f * v2 * (1.0f + erff(v2 * 0.70710678118654752f));
        ha.w = 0.5f * v3 * (1.0f + erff(v3 * 0.70710678118654752f));
        float w0 = accB.x + sb.x, w1 = accB.y + sb.y, w2 = accB.z + sb.z, w3 = accB.w + sb.w;
        hb.x = 0.5f * w0 * (1.0f + erff(w0 * 0.70710678118654752f));
        hb.y = 0.5f * w1 * (1.0f + erff(w1 * 0.70710678118654752f));
        hb.z = 0.5f * w2 * (1.0f + erff(w2 * 0.70710678118654752f));
        hb.w = 0.5f * w3 * (1.0f + erff(w3 * 0.70710678118654752f));
    }
    *(float4*)&hout[(size_t)warp * 256 + lane * 4] = ha;
    *(float4*)&hout[(size_t)warp * 256 + 128 + lane * 4] = hb;
}

// ---------------- scores: g = tanh(t1)*sigmoid(t2); scores = g @ Wc + bc ----------------
__global__ void scores_kernel(const float* __restrict__ Wc, const float* __restrict__ bc) {
    int warp = (blockIdx.x * blockDim.x + threadIdx.x) >> 5;
    int lane = threadIdx.x & 31;
    if (warp >= N_NODES) return;
    const float* t = g_T + (size_t)warp * 512;
    float acc0 = 0.f, acc1 = 0.f;
    #pragma unroll
    for (int half = 0; half < 2; half++) {
        int c0 = half * 128 + lane * 4;
        float4 t1 = *(const float4*)&t[c0];
        float4 t2 = *(const float4*)&t[256 + c0];
        float g0 = tanhf(t1.x) * (1.f / (1.f + expf(-t2.x)));
        float g1 = tanhf(t1.y) * (1.f / (1.f + expf(-t2.y)));
        float g2 = tanhf(t1.z) * (1.f / (1.f + expf(-t2.z)));
        float g3 = tanhf(t1.w) * (1.f / (1.f + expf(-t2.w)));
        acc0 += g0 * Wc[(c0 + 0) * 2] + g1 * Wc[(c0 + 1) * 2] + g2 * Wc[(c0 + 2) * 2] + g3 * Wc[(c0 + 3) * 2];
        acc1 += g0 * Wc[(c0 + 0) * 2 + 1] + g1 * Wc[(c0 + 1) * 2 + 1] + g2 * Wc[(c0 + 2) * 2 + 1] + g3 * Wc[(c0 + 3) * 2 + 1];
    }
    #pragma unroll
    for (int o = 16; o > 0; o >>= 1) {
        acc0 += __shfl_down_sync(0xffffffffu, acc0, o);
        acc1 += __shfl_down_sync(0xffffffffu, acc1, o);
    }
    if (lane == 0) {
        float s0 = acc0 + bc[0];
        float s1 = acc1 + bc[1];
        g_scores[2 * warp]     = s0;
        g_scores[2 * warp + 1] = s1;
        atomicMax(&g_smax[0], fmapU(s0));
        atomicMax(&g_smax[1], fmapU(s1));
    }
}

// ---------------- softmax denominators over all nodes ----------------
__global__ void sumexp_kernel() {
    float m0 = funmapU(g_smax[0]);
    float m1 = funmapU(g_smax[1]);
    int i = blockIdx.x * blockDim.x + threadIdx.x;
    int stride = gridDim.x * blockDim.x;
    float e0 = 0.f, e1 = 0.f;
    for (int n = i; n < N_NODES; n += stride) {
        e0 += expf(g_scores[2 * n]     - m0);
        e1 += expf(g_scores[2 * n + 1] - m1);
    }
    #pragma unroll
    for (int o = 16; o > 0; o >>= 1) {
        e0 += __shfl_down_sync(0xffffffffu, e0, o);
        e1 += __shfl_down_sync(0xffffffffu, e1, o);
    }
    if ((threadIdx.x & 31) == 0) {
        atomicAdd(&g_ssum[0], e0);
        atomicAdd(&g_ssum[1], e1);
    }
}

// ---------------- finalize: A = attn[:,label]; y = attn^T @ h ----------------
#define CHUNK 128
__global__ __launch_bounds__(256) void finalize_kernel(
    const float* __restrict__ h, const int* __restrict__ label,
    float* __restrict__ y, float* __restrict__ A)
{
    __shared__ float sA0[CHUNK], sA1[CHUNK];
    float m0 = funmapU(g_smax[0]);
    float m1 = funmapU(g_smax[1]);
    float inv0 = 1.f / g_ssum[0];
    float inv1 = 1.f / g_ssum[1];
    int base = blockIdx.x * CHUNK;
    int t = threadIdx.x;
    int lab = label ? *label : 1;
    if (t < CHUNK) {
        int n = base + t;
        if (n < N_NODES) {
            float a0 = expf(g_scores[2 * n]     - m0) * inv0;
            float a1 = expf(g_scores[2 * n + 1] - m1) * inv1;
            sA0[t] = a0;
            sA1[t] = a1;
            A[n] = lab ? a1 : a0;
        } else {
            sA0[t] = 0.f;
            sA1[t] = 0.f;
        }
    }
    __syncthreads();
    float y0 = 0.f, y1 = 0.f;
    int nmax = N_NODES - base;
    if (nmax > CHUNK) nmax = CHUNK;
    for (int j = 0; j < nmax; j++) {
        float hv = h[(size_t)(base + j) * 256 + t];
        y0 += sA0[j] * hv;
        y1 += sA1[j] * hv;
    }
    atomicAdd(&y[t],       y0);
    atomicAdd(&y[256 + t], y1);
}

// ---------------- launch ----------------
extern "C" void kernel_launch(void* const* d_in, const int* in_sizes, int n_in,
                              void* d_out, int out_size)
{
    const float* x  = (const float*)d_in[0];
    const float* Wq = (const float*)d_in[1];
    const float* bq = (const float*)d_in[2];
    const float* Wk = (const float*)d_in[3];
    const float* bk = (const float*)d_in[4];
    const float* Wv = (const float*)d_in[5];
    const float* bv = (const float*)d_in[6];
    const float* Ws = (const float*)d_in[7];
    const float* bs = (const float*)d_in[8];
    const float* Wa = (const float*)d_in[9];
    const float* ba = (const float*)d_in[10];
    const float* Wb = (const float*)d_in[11];
    const float* bb = (const float*)d_in[12];
    const float* Wc = (const float*)d_in[13];
    const float* bc = (const float*)d_in[14];
    const int*   ei = (const int*)d_in[15];
    const int*   lab = (n_in > 16) ? (const int*)d_in[16] : nullptr;

    float* out = (float*)d_out;
    float* y = out;                       // [2, 256]
    float* A = out + 512;                 // [50000]
    float* h = out + 512 + N_NODES;       // [50000, 256]

    float *pZ, *pW1, *pb1, *pT, *pW2, *pb2;
    cudaGetSymbolAddress((void**)&pZ,  g_Z);
    cudaGetSymbolAddress((void**)&pW1, g_W1);
    cudaGetSymbolAddress((void**)&pb1, g_b1);
    cudaGetSymbolAddress((void**)&pT,  g_T);
    cudaGetSymbolAddress((void**)&pW2, g_W2);
    cudaGetSymbolAddress((void**)&pb2, g_b2);

    pack1_kernel<<<(L_IN * 1024 + 255) / 256, 256>>>(Wq, Wk, Wv, Ws, bq, bk, bv, bs);
    pack2_kernel<<<(D_HID * 512 + 255) / 256, 256>>>(Wa, Wb, ba, bb);
    init_kernel<<<256, 256>>>(y);

    // Z = x @ [Wq|Wk|Wv|Ws] + bias   (M=50000, N=1024, K=1024)  — TF32 tensor cores
    gemm_tf32_bias<<<dim3(1024 / BN, (N_NODES + BM - 1) / BM), 256>>>(
        x, pW1, pb1, pZ, N_NODES, 1024, 1024);

    // CSR build
    count_kernel<<<(N_EDGES + 255) / 256, 256>>>(ei);
    scan_kernel<<<1, 1024>>>();
    fill_kernel<<<(N_EDGES + 255) / 256, 256>>>(ei);

    // edge softmax numerators
    edge_alpha_kernel<<<(N_EDGES * 32 + 255) / 256, 256>>>(ei);

    // per-node gather (den + weighted v sum) fused with gelu -> h
    gather_kernel<<<(N_NODES * 32 + 255) / 256, 256>>>(h);

    // T = h @ [Wa|Wb] + bias   (M=50000, N=512, K=256)
    gemm_tf32_bias<<<dim3(512 / BN, (N_NODES + BM - 1) / BM), 256>>>(
        h, pW2, pb2, pT, N_NODES, 512, 256);

    scores_kernel<<<(N_NODES * 32 + 255) / 256, 256>>>(Wc, bc);
    sumexp_kernel<<<256, 256>>>();
    finalize_kernel<<<(N_NODES + CHUNK - 1) / CHUNK, 256>>>(h, lab, y, A);
}

// round 9
// speedup vs baseline: 1.7656x; 1.3635x over previous
#include <cuda_runtime.h>
#include <mma.h>
#include <math.h>
#include <stdint.h>

using namespace nvcuda;

#define N_NODES 50000
#define ZROWS   50048          // padded to multiple of 128 for guard-free C stores
#define N_EDGES 800000
#define L_IN    1024
#define D_HID   256

// ---------------- scratch (device globals; no allocation allowed) ----------------
__device__ float g_Z[(size_t)ZROWS * 1024];     // [q | k | v | s] per node (no bias)
__device__ float g_W1[(size_t)L_IN * 1024];     // packed [Wq|Wk|Wv|Ws]
__device__ float g_T[(size_t)ZROWS * 512];      // [h@Wa | h@Wb] (no bias)
__device__ float g_W2[(size_t)D_HID * 512];     // packed [Wa|Wb]
__device__ float g_ex[N_EDGES];
__device__ float g_scores[N_NODES * 2];
__device__ unsigned g_smax[2];
__device__ float g_ssum[2];
// CSR scratch
__device__ int g_cnt[N_NODES];
__device__ int g_off[N_NODES];
__device__ int g_cur[N_NODES];
__device__ int g_srcs[N_EDGES];

// monotone float<->uint map for atomicMax on signed floats
__device__ __forceinline__ unsigned fmapU(float f) {
    int i = __float_as_int(f);
    return (i < 0) ? ~((unsigned)i) : (((unsigned)i) | 0x80000000u);
}
__device__ __forceinline__ float funmapU(unsigned u) {
    int i = (u & 0x80000000u) ? (int)(u & 0x7fffffffu) : (int)(~u);
    return __int_as_float(i);
}

// ---------------- pack kernels (weights only; biases folded into consumers) ----------------
__global__ void pack1_kernel(const float* __restrict__ Wq, const float* __restrict__ Wk,
                             const float* __restrict__ Wv, const float* __restrict__ Ws) {
    int i = blockIdx.x * blockDim.x + threadIdx.x;
    if (i < L_IN * 1024) {
        int k = i >> 10, c = i & 1023;
        int m = c >> 8, lc = c & 255;
        const float* W = (m == 0) ? Wq : (m == 1) ? Wk : (m == 2) ? Wv : Ws;
        g_W1[i] = W[k * 256 + lc];
    }
}

__global__ void pack2_kernel(const float* __restrict__ Wa, const float* __restrict__ Wb) {
    int i = blockIdx.x * blockDim.x + threadIdx.x;
    if (i < D_HID * 512) {
        int k = i >> 9, c = i & 511;
        int m = c >> 8, lc = c & 255;
        const float* W = (m == 0) ? Wa : Wb;
        g_W2[i] = W[k * 256 + lc];
    }
}

// ---------------- init ----------------
__global__ void init_kernel(float* __restrict__ y) {
    int i = blockIdx.x * blockDim.x + threadIdx.x;
    int stride = gridDim.x * blockDim.x;
    for (int j = i; j < N_NODES; j += stride) g_cnt[j] = 0;
    if (i < 512) y[i] = 0.f;
    if (i < 2) { g_ssum[i] = 0.f; g_smax[i] = 0u; }
}

// ---------------- TF32 GEMM v2: C[M,N] = A[M,K] @ B[K,N] ----------------
// BM=128, BN=128, BK=32. 128 threads = 4 warps (2x2), each warp 64x64.
// cp.async double-buffered; no bias; direct fragment stores (C rows padded).
#define BM 128
#define BN 128
#define BK 32
#define APITCH (BK + 4)     // 36 floats, 144B (16B-aligned)
#define BPITCH (BN + 4)     // 132 floats, 528B (16B-aligned)
#define ASZ (BM * APITCH)
#define BSZ (BK * BPITCH)
#define GEMM_SMEM ((2 * ASZ + 2 * BSZ) * 4)

__device__ __forceinline__ void cp16(uint32_t s, const float* g, bool ok) {
    int sz = ok ? 16 : 0;
    asm volatile("cp.async.cg.shared.global [%0], [%1], 16, %2;" :: "r"(s), "l"(g), "r"(sz));
}

__global__ __launch_bounds__(128) void gemm_tf32(
    const float* __restrict__ A, const float* __restrict__ B,
    float* __restrict__ C, int M, int N, int K)
{
    extern __shared__ float sm[];
    float* As = sm;               // [2][BM][APITCH]
    float* Bs = sm + 2 * ASZ;     // [2][BK][BPITCH]
    uint32_t sAs = (uint32_t)__cvta_generic_to_shared(As);
    uint32_t sBs = (uint32_t)__cvta_generic_to_shared(Bs);

    int n0 = blockIdx.x * BN;
    int m0 = blockIdx.y * BM;
    int tid = threadIdx.x;
    int warpId = tid >> 5;
    int wm0 = (warpId & 1) * 64;
    int wn0 = (warpId >> 1) * 64;

    // A load mapping: 8 iters, row = (tid>>3)+j*16, kchunk = tid&7
    int a_r0 = tid >> 3;
    int a_q  = (tid & 7) * 4;
    // B load mapping: 8 iters, krow = (tid>>5)+j*4, nchunk = tid&31
    int b_k0 = tid >> 5;
    int b_q  = (tid & 31) * 4;

    wmma::fragment<wmma::accumulator, 16, 16, 8, float> acc[4][4];
    #pragma unroll
    for (int i = 0; i < 4; i++)
        #pragma unroll
        for (int j = 0; j < 4; j++)
            wmma::fill_fragment(acc[i][j], 0.0f);

    int nT = K / BK;

    // ---- tile loader ----
    auto loadTile = [&](int buf, int kk) {
        #pragma unroll
        for (int j = 0; j < 8; j++) {
            int r = a_r0 + j * 16;
            int gm = m0 + r;
            cp16(sAs + (buf * ASZ + r * APITCH + a_q) * 4,
                 A + (size_t)gm * K + kk + a_q, gm < M);
        }
        #pragma unroll
        for (int j = 0; j < 8; j++) {
            int kr = b_k0 + j * 4;
            cp16(sBs + (buf * BSZ + kr * BPITCH + b_q) * 4,
                 B + (size_t)(kk + kr) * N + n0 + b_q, true);
        }
        asm volatile("cp.async.commit_group;");
    };

    loadTile(0, 0);

    for (int t = 0; t < nT; t++) {
        if (t + 1 < nT) {
            loadTile((t + 1) & 1, (t + 1) * BK);
            asm volatile("cp.async.wait_group 1;");
        } else {
            asm volatile("cp.async.wait_group 0;");
        }
        __syncthreads();

        int buf = t & 1;
        const float* Ab = As + buf * ASZ;
        const float* Bb = Bs + buf * BSZ;
        #pragma unroll
        for (int ks = 0; ks < BK; ks += 8) {
            wmma::fragment<wmma::matrix_a, 16, 16, 8, wmma::precision::tf32, wmma::row_major> af[4];
            wmma::fragment<wmma::matrix_b, 16, 16, 8, wmma::precision::tf32, wmma::row_major> bf[4];
            #pragma unroll
            for (int i = 0; i < 4; i++) {
                wmma::load_matrix_sync(af[i], &Ab[(wm0 + i * 16) * APITCH + ks], APITCH);
                #pragma unroll
                for (int e = 0; e < af[i].num_elements; e++)
                    af[i].x[e] = wmma::__float_to_tf32(af[i].x[e]);
            }
            #pragma unroll
            for (int j = 0; j < 4; j++) {
                wmma::load_matrix_sync(bf[j], &Bb[ks * BPITCH + wn0 + j * 16], BPITCH);
                #pragma unroll
                for (int e = 0; e < bf[j].num_elements; e++)
                    bf[j].x[e] = wmma::__float_to_tf32(bf[j].x[e]);
            }
            #pragma unroll
            for (int i = 0; i < 4; i++)
                #pragma unroll
                for (int j = 0; j < 4; j++)
                    wmma::mma_sync(acc[i][j], af[i], bf[j], acc[i][j]);
        }
        __syncthreads();
    }

    // direct stores — C has padded rows, no guards needed
    #pragma unroll
    for (int i = 0; i < 4; i++)
        #pragma unroll
        for (int j = 0; j < 4; j++)
            wmma::store_matrix_sync(&C[(size_t)(m0 + wm0 + i * 16) * N + n0 + wn0 + j * 16],
                                    acc[i][j], N, wmma::mem_row_major);
}

// ---------------- CSR build ----------------
__global__ void count_kernel(const int* __restrict__ ei) {
    int i = blockIdx.x * blockDim.x + threadIdx.x;
    if (i < N_EDGES) atomicAdd(&g_cnt[ei[N_EDGES + i]], 1);
}

__global__ __launch_bounds__(1024) void scan_kernel() {
    __shared__ int part[1024];
    const int CH = (N_NODES + 1023) / 1024;
    int t = threadIdx.x;
    int base = t * CH;
    int s = 0;
    for (int j = 0; j < CH; j++) {
        int idx = base + j;
        if (idx < N_NODES) s += g_cnt[idx];
    }
    part[t] = s;
    __syncthreads();
    for (int off = 1; off < 1024; off <<= 1) {
        int v = (t >= off) ? part[t - off] : 0;
        __syncthreads();
        part[t] += v;
        __syncthreads();
    }
    int run = part[t] - s;
    for (int j = 0; j < CH; j++) {
        int idx = base + j;
        if (idx < N_NODES) {
            g_off[idx] = run;
            g_cur[idx] = run;
            run += g_cnt[idx];
        }
    }
}

__global__ void fill_kernel(const int* __restrict__ ei) {
    int i = blockIdx.x * blockDim.x + threadIdx.x;
    if (i >= N_EDGES) return;
    int src = ei[i];
    int dst = ei[N_EDGES + i];
    int pos = atomicAdd(&g_cur[dst], 1);
    g_srcs[pos] = src;
}

// ---------------- fused per-node edge softmax + gather + gelu ----------------
// warp per node. Pass1: alpha/exp/den over in-edges (q resident in regs).
// Pass2: msg = sum w*v. h = gelu(msg + bv + s + bs).
__global__ void edge_fused_kernel(const float* __restrict__ bq, const float* __restrict__ bk,
                                  const float* __restrict__ bv, const float* __restrict__ bs,
                                  float* __restrict__ hout) {
    int warp = (blockIdx.x * blockDim.x + threadIdx.x) >> 5;
    int lane = threadIdx.x & 31;
    if (warp >= N_NODES) return;
    int start = g_off[warp];
    int deg = g_cnt[warp];

    const float* qp = g_Z + (size_t)warp * 1024;
    float4 q0 = *(const float4*)&qp[lane * 4];
    float4 q1 = *(const float4*)&qp[128 + lane * 4];
    {
        float4 bq0 = *(const float4*)&bq[lane * 4];
        float4 bq1 = *(const float4*)&bq[128 + lane * 4];
        q0.x += bq0.x; q0.y += bq0.y; q0.z += bq0.z; q0.w += bq0.w;
        q1.x += bq1.x; q1.y += bq1.y; q1.z += bq1.z; q1.w += bq1.w;
    }
    float4 bk0 = *(const float4*)&bk[lane * 4];
    float4 bk1 = *(const float4*)&bk[128 + lane * 4];

    // pass 1: numerators + denominator
    float den = 0.f;
    for (int i = 0; i < deg; i++) {
        int src = g_srcs[start + i];
        const float* kp = g_Z + (size_t)src * 1024 + 256;
        float4 k0 = *(const float4*)&kp[lane * 4];
        float4 k1 = *(const float4*)&kp[128 + lane * 4];
        float s = q0.x * (k0.x + bk0.x) + q0.y * (k0.y + bk0.y)
                + q0.z * (k0.z + bk0.z) + q0.w * (k0.w + bk0.w)
                + q1.x * (k1.x + bk1.x) + q1.y * (k1.y + bk1.y)
                + q1.z * (k1.z + bk1.z) + q1.w * (k1.w + bk1.w);
        #pragma unroll
        for (int o = 16; o > 0; o >>= 1) s += __shfl_xor_sync(0xffffffffu, s, o);
        float ex = expf(s * 0.0625f);   // softmax max-shift skipped: mathematically identical
        if (lane == 0) g_ex[start + i] = ex;
        den += ex;
    }
    float inv = 1.f / (den + 1e-16f);

    // pass 2: weighted message
    float4 accA = make_float4(0.f, 0.f, 0.f, 0.f);
    float4 accB = make_float4(0.f, 0.f, 0.f, 0.f);
    for (int i = 0; i < deg; i++) {
        int src = g_srcs[start + i];
        float w = g_ex[start + i] * inv;
        const float* v = g_Z + (size_t)src * 1024 + 512;
        float4 va = *(const float4*)&v[lane * 4];
        float4 vb = *(const float4*)&v[128 + lane * 4];
        accA.x += w * va.x; accA.y += w * va.y; accA.z += w * va.z; accA.w += w * va.w;
        accB.x += w * vb.x; accB.y += w * vb.y; accB.z += w * vb.z; accB.w += w * vb.w;
    }

    // h = gelu(msg + bv*(deg>0) + s + bs)   (sum of weights == 1 folds bv out of the loop)
    float bvs = (deg > 0) ? 1.f : 0.f;
    const float* sp = g_Z + (size_t)warp * 1024 + 768;
    float4 sa = *(const float4*)&sp[lane * 4];
    float4 sb = *(const float4*)&sp[128 + lane * 4];
    float4 bsa = *(const float4*)&bs[lane * 4];
    float4 bsb = *(const float4*)&bs[128 + lane * 4];
    float4 bva = *(const float4*)&bv[lane * 4];
    float4 bvb = *(const float4*)&bv[128 + lane * 4];
    float4 ha, hb;
    {
        float v0 = accA.x + bvs * bva.x + sa.x + bsa.x;
        float v1 = accA.y + bvs * bva.y + sa.y + bsa.y;
        float v2 = accA.z + bvs * bva.z + sa.z + bsa.z;
        float v3 = accA.w + bvs * bva.w + sa.w + bsa.w;
        ha.x = 0.5f * v0 * (1.0f + erff(v0 * 0.70710678118654752f));
        ha.y = 0.5f * v1 * (1.0f + erff(v1 * 0.70710678118654752f));
        ha.z = 0.5f * v2 * (1.0f + erff(v2 * 0.70710678118654752f));
        ha.w = 0.5f * v3 * (1.0f + erff(v3 * 0.70710678118654752f));
        float w0 = accB.x + bvs * bvb.x + sb.x + bsb.x;
        float w1 = accB.y + bvs * bvb.y + sb.y + bsb.y;
        float w2 = accB.z + bvs * bvb.z + sb.z + bsb.z;
        float w3 = accB.w + bvs * bvb.w + sb.w + bsb.w;
        hb.x = 0.5f * w0 * (1.0f + erff(w0 * 0.70710678118654752f));
        hb.y = 0.5f * w1 * (1.0f + erff(w1 * 0.70710678118654752f));
        hb.z = 0.5f * w2 * (1.0f + erff(w2 * 0.70710678118654752f));
        hb.w = 0.5f * w3 * (1.0f + erff(w3 * 0.70710678118654752f));
    }
    *(float4*)&hout[(size_t)warp * 256 + lane * 4] = ha;
    *(float4*)&hout[(size_t)warp * 256 + 128 + lane * 4] = hb;
}

// ---------------- scores: g = tanh(T1+ba)*sigmoid(T2+bb); scores = g @ Wc + bc ----------------
__global__ void scores_kernel(const float* __restrict__ Wc, const float* __restrict__ bc,
                              const float* __restrict__ ba, const float* __restrict__ bb) {
    int warp = (blockIdx.x * blockDim.x + threadIdx.x) >> 5;
    int lane = threadIdx.x & 31;
    if (warp >= N_NODES) return;
    const float* t = g_T + (size_t)warp * 512;
    float acc0 = 0.f, acc1 = 0.f;
    #pragma unroll
    for (int half = 0; half < 2; half++) {
        int c0 = half * 128 + lane * 4;
        float4 t1 = *(const float4*)&t[c0];
        float4 t2 = *(const float4*)&t[256 + c0];
        float4 a4 = *(const float4*)&ba[c0];
        float4 b4 = *(const float4*)&bb[c0];
        float g0 = tanhf(t1.x + a4.x) * (1.f / (1.f + expf(-(t2.x + b4.x))));
        float g1 = tanhf(t1.y + a4.y) * (1.f / (1.f + expf(-(t2.y + b4.y))));
        float g2 = tanhf(t1.z + a4.z) * (1.f / (1.f + expf(-(t2.z + b4.z))));
        float g3 = tanhf(t1.w + a4.w) * (1.f / (1.f + expf(-(t2.w + b4.w))));
        acc0 += g0 * Wc[(c0 + 0) * 2] + g1 * Wc[(c0 + 1) * 2] + g2 * Wc[(c0 + 2) * 2] + g3 * Wc[(c0 + 3) * 2];
        acc1 += g0 * Wc[(c0 + 0) * 2 + 1] + g1 * Wc[(c0 + 1) * 2 + 1] + g2 * Wc[(c0 + 2) * 2 + 1] + g3 * Wc[(c0 + 3) * 2 + 1];
    }
    #pragma unroll
    for (int o = 16; o > 0; o >>= 1) {
        acc0 += __shfl_down_sync(0xffffffffu, acc0, o);
        acc1 += __shfl_down_sync(0xffffffffu, acc1, o);
    }
    if (lane == 0) {
        float s0 = acc0 + bc[0];
        float s1 = acc1 + bc[1];
        g_scores[2 * warp]     = s0;
        g_scores[2 * warp + 1] = s1;
        atomicMax(&g_smax[0], fmapU(s0));
        atomicMax(&g_smax[1], fmapU(s1));
    }
}

// ---------------- softmax denominators over all nodes ----------------
__global__ void sumexp_kernel() {
    float m0 = funmapU(g_smax[0]);
    float m1 = funmapU(g_smax[1]);
    int i = blockIdx.x * blockDim.x + threadIdx.x;
    int stride = gridDim.x * blockDim.x;
    float e0 = 0.f, e1 = 0.f;
    for (int n = i; n < N_NODES; n += stride) {
        e0 += expf(g_scores[2 * n]     - m0);
        e1 += expf(g_scores[2 * n + 1] - m1);
    }
    #pragma unroll
    for (int o = 16; o > 0; o >>= 1) {
        e0 += __shfl_down_sync(0xffffffffu, e0, o);
        e1 += __shfl_down_sync(0xffffffffu, e1, o);
    }
    if ((threadIdx.x & 31) == 0) {
        atomicAdd(&g_ssum[0], e0);
        atomicAdd(&g_ssum[1], e1);
    }
}

// ---------------- finalize: A = attn[:,label]; y = attn^T @ h ----------------
#define CHUNK 128
__global__ __launch_bounds__(256) void finalize_kernel(
    const float* __restrict__ h, const int* __restrict__ label,
    float* __restrict__ y, float* __restrict__ A)
{
    __shared__ float sA0[CHUNK], sA1[CHUNK];
    float m0 = funmapU(g_smax[0]);
    float m1 = funmapU(g_smax[1]);
    float inv0 = 1.f / g_ssum[0];
    float inv1 = 1.f / g_ssum[1];
    int base = blockIdx.x * CHUNK;
    int t = threadIdx.x;
    int lab = label ? *label : 1;
    if (t < CHUNK) {
        int n = base + t;
        if (n < N_NODES) {
            float a0 = expf(g_scores[2 * n]     - m0) * inv0;
            float a1 = expf(g_scores[2 * n + 1] - m1) * inv1;
            sA0[t] = a0;
            sA1[t] = a1;
            A[n] = lab ? a1 : a0;
        } else {
            sA0[t] = 0.f;
            sA1[t] = 0.f;
        }
    }
    __syncthreads();
    float y0 = 0.f, y1 = 0.f;
    int nmax = N_NODES - base;
    if (nmax > CHUNK) nmax = CHUNK;
    for (int j = 0; j < nmax; j++) {
        float hv = h[(size_t)(base + j) * 256 + t];
        y0 += sA0[j] * hv;
        y1 += sA1[j] * hv;
    }
    atomicAdd(&y[t],       y0);
    atomicAdd(&y[256 + t], y1);
}

// ---------------- launch ----------------
extern "C" void kernel_launch(void* const* d_in, const int* in_sizes, int n_in,
                              void* d_out, int out_size)
{
    const float* x  = (const float*)d_in[0];
    const float* Wq = (const float*)d_in[1];
    const float* bq = (const float*)d_in[2];
    const float* Wk = (const float*)d_in[3];
    const float* bk = (const float*)d_in[4];
    const float* Wv = (const float*)d_in[5];
    const float* bv = (const float*)d_in[6];
    const float* Ws = (const float*)d_in[7];
    const float* bs = (const float*)d_in[8];
    const float* Wa = (const float*)d_in[9];
    const float* ba = (const float*)d_in[10];
    const float* Wb = (const float*)d_in[11];
    const float* bb = (const float*)d_in[12];
    const float* Wc = (const float*)d_in[13];
    const float* bc = (const float*)d_in[14];
    const int*   ei = (const int*)d_in[15];
    const int*   lab = (n_in > 16) ? (const int*)d_in[16] : nullptr;

    float* out = (float*)d_out;
    float* y = out;                       // [2, 256]
    float* A = out + 512;                 // [50000]
    float* h = out + 512 + N_NODES;       // [50000, 256]

    float *pZ, *pW1, *pT, *pW2;
    cudaGetSymbolAddress((void**)&pZ,  g_Z);
    cudaGetSymbolAddress((void**)&pW1, g_W1);
    cudaGetSymbolAddress((void**)&pT,  g_T);
    cudaGetSymbolAddress((void**)&pW2, g_W2);

    cudaFuncSetAttribute(gemm_tf32, cudaFuncAttributeMaxDynamicSharedMemorySize, GEMM_SMEM);

    pack1_kernel<<<(L_IN * 1024 + 255) / 256, 256>>>(Wq, Wk, Wv, Ws);
    pack2_kernel<<<(D_HID * 512 + 255) / 256, 256>>>(Wa, Wb);
    init_kernel<<<256, 256>>>(y);

    // CSR build (independent of GEMM; cheap)
    count_kernel<<<(N_EDGES + 255) / 256, 256>>>(ei);
    scan_kernel<<<1, 1024>>>();
    fill_kernel<<<(N_EDGES + 255) / 256, 256>>>(ei);

    // Z = x @ [Wq|Wk|Wv|Ws]   (M=50000 padded to 50048, N=1024, K=1024)
    gemm_tf32<<<dim3(1024 / BN, ZROWS / BM), 128, GEMM_SMEM>>>(
        x, pW1, pZ, N_NODES, 1024, 1024);

    // fused per-node edge softmax + gather + gelu -> h
    edge_fused_kernel<<<(N_NODES * 32 + 255) / 256, 256>>>(bq, bk, bv, bs, h);

    // T = h @ [Wa|Wb]   (M=50000 padded, N=512, K=256)
    gemm_tf32<<<dim3(512 / BN, ZROWS / BM), 128, GEMM_SMEM>>>(
        h, pW2, pT, N_NODES, 512, 256);

    scores_kernel<<<(N_NODES * 32 + 255) / 256, 256>>>(Wc, bc, ba, bb);
    sumexp_kernel<<<256, 256>>>();
    finalize_kernel<<<(N_NODES + CHUNK - 1) / CHUNK, 256>>>(h, lab, y, A);
}

// round 10
// speedup vs baseline: 1.7770x; 1.0065x over previous
#include <cuda_runtime.h>
#include <mma.h>
#include <math.h>
#include <stdint.h>

using namespace nvcuda;

#define N_NODES 50000
#define ZROWS   50176          // padded to multiple of 256 for guard-free C stores
#define N_EDGES 800000
#define L_IN    1024
#define D_HID   256

// ---------------- scratch (device globals; no allocation allowed) ----------------
__device__ float g_Z[(size_t)ZROWS * 1024];     // [q | k | v | s] per node (no bias)
__device__ float g_W1[(size_t)L_IN * 1024];     // packed [Wq|Wk|Wv|Ws]
__device__ float g_T[(size_t)ZROWS * 512];      // [h@Wa | h@Wb] (no bias)
__device__ float g_W2[(size_t)D_HID * 512];     // packed [Wa|Wb]
__device__ float g_scores[N_NODES * 2];
__device__ unsigned g_smax[2];
__device__ float g_ssum[2];
// CSR scratch
__device__ int g_cnt[N_NODES];
__device__ int g_off[N_NODES];
__device__ int g_cur[N_NODES];
__device__ int g_srcs[N_EDGES];

// monotone float<->uint map for atomicMax on signed floats
__device__ __forceinline__ unsigned fmapU(float f) {
    int i = __float_as_int(f);
    return (i < 0) ? ~((unsigned)i) : (((unsigned)i) | 0x80000000u);
}
__device__ __forceinline__ float funmapU(unsigned u) {
    int i = (u & 0x80000000u) ? (int)(u & 0x7fffffffu) : (int)(~u);
    return __int_as_float(i);
}

// ---------------- pack kernels (weights only; biases folded into consumers) ----------------
__global__ void pack1_kernel(const float* __restrict__ Wq, const float* __restrict__ Wk,
                             const float* __restrict__ Wv, const float* __restrict__ Ws) {
    int i = blockIdx.x * blockDim.x + threadIdx.x;
    if (i < L_IN * 1024) {
        int k = i >> 10, c = i & 1023;
        int m = c >> 8, lc = c & 255;
        const float* W = (m == 0) ? Wq : (m == 1) ? Wk : (m == 2) ? Wv : Ws;
        g_W1[i] = W[k * 256 + lc];
    }
}

__global__ void pack2_kernel(const float* __restrict__ Wa, const float* __restrict__ Wb) {
    int i = blockIdx.x * blockDim.x + threadIdx.x;
    if (i < D_HID * 512) {
        int k = i >> 9, c = i & 511;
        int m = c >> 8, lc = c & 255;
        const float* W = (m == 0) ? Wa : Wb;
        g_W2[i] = W[k * 256 + lc];
    }
}

// ---------------- init ----------------
__global__ void init_kernel(float* __restrict__ y) {
    int i = blockIdx.x * blockDim.x + threadIdx.x;
    int stride = gridDim.x * blockDim.x;
    for (int j = i; j < N_NODES; j += stride) g_cnt[j] = 0;
    if (i < 512) y[i] = 0.f;
    if (i < 2) { g_ssum[i] = 0.f; g_smax[i] = 0u; }
}

// ---------------- TF32 GEMM v3: C[M,N] = A[M,K] @ B[K,N] ----------------
// BM=256, BN=128, BK=32, 3-stage cp.async, 256 threads = 8 warps (4x2), 64x64 each.
#define BM 256
#define BN 128
#define BK 32
#define NSTG 3
#define APITCH (BK + 4)     // 36 floats
#define BPITCH (BN + 4)     // 132 floats
#define ASZ (BM * APITCH)   // 9216
#define BSZ (BK * BPITCH)   // 4224
#define GEMM_SMEM (NSTG * (ASZ + BSZ) * 4)   // 161280 B

__device__ __forceinline__ void cp16(uint32_t s, const float* g, bool ok) {
    int sz = ok ? 16 : 0;
    asm volatile("cp.async.cg.shared.global [%0], [%1], 16, %2;" :: "r"(s), "l"(g), "r"(sz));
}

__global__ __launch_bounds__(256) void gemm_tf32(
    const float* __restrict__ A, const float* __restrict__ B,
    float* __restrict__ C, int M, int N, int K)
{
    extern __shared__ float sm[];
    float* As = sm;                     // [NSTG][BM][APITCH]
    float* Bs = sm + NSTG * ASZ;        // [NSTG][BK][BPITCH]
    uint32_t sAs = (uint32_t)__cvta_generic_to_shared(As);
    uint32_t sBs = (uint32_t)__cvta_generic_to_shared(Bs);

    int n0 = blockIdx.x * BN;
    int m0 = blockIdx.y * BM;
    int tid = threadIdx.x;
    int warpId = tid >> 5;
    int wm0 = (warpId & 3) * 64;
    int wn0 = (warpId >> 2) * 64;

    // A load mapping: 8 iters, row = (tid>>3)+j*32, kchunk = (tid&7)*4
    int a_r0 = tid >> 3;
    int a_q  = (tid & 7) * 4;
    // B load mapping: 4 iters, krow = (tid>>5)+j*8, nchunk = (tid&31)*4
    int b_k0 = tid >> 5;
    int b_q  = (tid & 31) * 4;

    wmma::fragment<wmma::accumulator, 16, 16, 8, float> acc[4][4];
    #pragma unroll
    for (int i = 0; i < 4; i++)
        #pragma unroll
        for (int j = 0; j < 4; j++)
            wmma::fill_fragment(acc[i][j], 0.0f);

    int nT = K / BK;

    auto loadTile = [&](int buf, int kk) {
        #pragma unroll
        for (int j = 0; j < 8; j++) {
            int r = a_r0 + j * 32;
            int gm = m0 + r;
            cp16(sAs + (buf * ASZ + r * APITCH + a_q) * 4,
                 A + (size_t)gm * K + kk + a_q, gm < M);
        }
        #pragma unroll
        for (int j = 0; j < 4; j++) {
            int kr = b_k0 + j * 8;
            cp16(sBs + (buf * BSZ + kr * BPITCH + b_q) * 4,
                 B + (size_t)(kk + kr) * N + n0 + b_q, true);
        }
        asm volatile("cp.async.commit_group;");
    };

    loadTile(0, 0);
    loadTile(1, BK);

    for (int t = 0; t < nT; t++) {
        if (t + 2 < nT) {
            loadTile((t + 2) % NSTG, (t + 2) * BK);
            asm volatile("cp.async.wait_group 2;");
        } else if (t + 1 < nT) {
            asm volatile("cp.async.wait_group 1;");
        } else {
            asm volatile("cp.async.wait_group 0;");
        }
        __syncthreads();

        int buf = t % NSTG;
        const float* Ab = As + buf * ASZ;
        const float* Bb = Bs + buf * BSZ;
        #pragma unroll
        for (int ks = 0; ks < BK; ks += 8) {
            wmma::fragment<wmma::matrix_a, 16, 16, 8, wmma::precision::tf32, wmma::row_major> af[4];
            wmma::fragment<wmma::matrix_b, 16, 16, 8, wmma::precision::tf32, wmma::row_major> bf[4];
            #pragma unroll
            for (int i = 0; i < 4; i++) {
                wmma::load_matrix_sync(af[i], &Ab[(wm0 + i * 16) * APITCH + ks], APITCH);
                #pragma unroll
                for (int e = 0; e < af[i].num_elements; e++)
                    af[i].x[e] = wmma::__float_to_tf32(af[i].x[e]);
            }
            #pragma unroll
            for (int j = 0; j < 4; j++) {
                wmma::load_matrix_sync(bf[j], &Bb[ks * BPITCH + wn0 + j * 16], BPITCH);
                #pragma unroll
                for (int e = 0; e < bf[j].num_elements; e++)
                    bf[j].x[e] = wmma::__float_to_tf32(bf[j].x[e]);
            }
            #pragma unroll
            for (int i = 0; i < 4; i++)
                #pragma unroll
                for (int j = 0; j < 4; j++)
                    wmma::mma_sync(acc[i][j], af[i], bf[j], acc[i][j]);
        }
        __syncthreads();
    }

    // direct stores — C rows padded to BM multiples, no guards needed
    #pragma unroll
    for (int i = 0; i < 4; i++)
        #pragma unroll
        for (int j = 0; j < 4; j++)
            wmma::store_matrix_sync(&C[(size_t)(m0 + wm0 + i * 16) * N + n0 + wn0 + j * 16],
                                    acc[i][j], N, wmma::mem_row_major);
}

// ---------------- CSR build ----------------
__global__ void count_kernel(const int* __restrict__ ei) {
    int i = blockIdx.x * blockDim.x + threadIdx.x;
    if (i < N_EDGES) atomicAdd(&g_cnt[ei[N_EDGES + i]], 1);
}

__global__ __launch_bounds__(1024) void scan_kernel() {
    __shared__ int part[1024];
    const int CH = (N_NODES + 1023) / 1024;
    int t = threadIdx.x;
    int base = t * CH;
    int s = 0;
    for (int j = 0; j < CH; j++) {
        int idx = base + j;
        if (idx < N_NODES) s += g_cnt[idx];
    }
    part[t] = s;
    __syncthreads();
    for (int off = 1; off < 1024; off <<= 1) {
        int v = (t >= off) ? part[t - off] : 0;
        __syncthreads();
        part[t] += v;
        __syncthreads();
    }
    int run = part[t] - s;
    for (int j = 0; j < CH; j++) {
        int idx = base + j;
        if (idx < N_NODES) {
            g_off[idx] = run;
            g_cur[idx] = run;
            run += g_cnt[idx];
        }
    }
}

__global__ void fill_kernel(const int* __restrict__ ei) {
    int i = blockIdx.x * blockDim.x + threadIdx.x;
    if (i >= N_EDGES) return;
    int src = ei[i];
    int dst = ei[N_EDGES + i];
    int pos = atomicAdd(&g_cur[dst], 1);
    g_srcs[pos] = src;
}

// ---------------- fused per-node SINGLE-PASS edge softmax + gather + gelu ----------------
// warp per node. msg = (sum ex_i * v_i) / (sum ex_i); k||v contiguous per src row.
__device__ __forceinline__ float dot8(const float4& a0, const float4& a1,
                                      const float4& b0, const float4& b1) {
    return a0.x * b0.x + a0.y * b0.y + a0.z * b0.z + a0.w * b0.w
         + a1.x * b1.x + a1.y * b1.y + a1.z * b1.z + a1.w * b1.w;
}

__global__ void edge_fused_kernel(const float* __restrict__ bq, const float* __restrict__ bk,
                                  const float* __restrict__ bv, const float* __restrict__ bs,
                                  float* __restrict__ hout) {
    int warp = (blockIdx.x * blockDim.x + threadIdx.x) >> 5;
    int lane = threadIdx.x & 31;
    if (warp >= N_NODES) return;
    int start = g_off[warp];
    int deg = g_cnt[warp];

    const float* qp = g_Z + (size_t)warp * 1024;
    float4 q0 = *(const float4*)&qp[lane * 4];
    float4 q1 = *(const float4*)&qp[128 + lane * 4];
    {
        float4 bq0 = *(const float4*)&bq[lane * 4];
        float4 bq1 = *(const float4*)&bq[128 + lane * 4];
        q0.x += bq0.x; q0.y += bq0.y; q0.z += bq0.z; q0.w += bq0.w;
        q1.x += bq1.x; q1.y += bq1.y; q1.z += bq1.z; q1.w += bq1.w;
    }
    // per-node constant: (q+bq)·bk
    float dqbk;
    {
        float4 bk0 = *(const float4*)&bk[lane * 4];
        float4 bk1 = *(const float4*)&bk[128 + lane * 4];
        dqbk = dot8(q0, q1, bk0, bk1);
        #pragma unroll
        for (int o = 16; o > 0; o >>= 1) dqbk += __shfl_xor_sync(0xffffffffu, dqbk, o);
    }

    float den = 0.f;
    float4 accA = make_float4(0.f, 0.f, 0.f, 0.f);
    float4 accB = make_float4(0.f, 0.f, 0.f, 0.f);

    int i = 0;
    for (; i + 1 < deg; i += 2) {
        int srcX = g_srcs[start + i];
        int srcY = g_srcs[start + i + 1];
        const float* kvX = g_Z + (size_t)srcX * 1024 + 256;   // k: +0..255, v: +256..511
        const float* kvY = g_Z + (size_t)srcY * 1024 + 256;
        float4 kX0 = *(const float4*)&kvX[lane * 4];
        float4 kX1 = *(const float4*)&kvX[128 + lane * 4];
        float4 kY0 = *(const float4*)&kvY[lane * 4];
        float4 kY1 = *(const float4*)&kvY[128 + lane * 4];
        float sX = dot8(q0, q1, kX0, kX1);
        float sY = dot8(q0, q1, kY0, kY1);
        #pragma unroll
        for (int o = 16; o > 0; o >>= 1) {
            sX += __shfl_xor_sync(0xffffffffu, sX, o);
            sY += __shfl_xor_sync(0xffffffffu, sY, o);
        }
        float exX = expf((sX + dqbk) * 0.0625f);   // max-shift skipped: identical
        float exY = expf((sY + dqbk) * 0.0625f);
        den += exX + exY;
        float4 vX0 = *(const float4*)&kvX[256 + lane * 4];
        float4 vX1 = *(const float4*)&kvX[384 + lane * 4];
        float4 vY0 = *(const float4*)&kvY[256 + lane * 4];
        float4 vY1 = *(const float4*)&kvY[384 + lane * 4];
        accA.x += exX * vX0.x + exY * vY0.x;
        accA.y += exX * vX0.y + exY * vY0.y;
        accA.z += exX * vX0.z + exY * vY0.z;
        accA.w += exX * vX0.w + exY * vY0.w;
        accB.x += exX * vX1.x + exY * vY1.x;
        accB.y += exX * vX1.y + exY * vY1.y;
        accB.z += exX * vX1.z + exY * vY1.z;
        accB.w += exX * vX1.w + exY * vY1.w;
    }
    if (i < deg) {
        int src = g_srcs[start + i];
        const float* kv = g_Z + (size_t)src * 1024 + 256;
        float4 k0 = *(const float4*)&kv[lane * 4];
        float4 k1 = *(const float4*)&kv[128 + lane * 4];
        float s = dot8(q0, q1, k0, k1);
        #pragma unroll
        for (int o = 16; o > 0; o >>= 1) s += __shfl_xor_sync(0xffffffffu, s, o);
        float ex = expf((s + dqbk) * 0.0625f);
        den += ex;
        float4 v0 = *(const float4*)&kv[256 + lane * 4];
        float4 v1 = *(const float4*)&kv[384 + lane * 4];
        accA.x += ex * v0.x; accA.y += ex * v0.y; accA.z += ex * v0.z; accA.w += ex * v0.w;
        accB.x += ex * v1.x; accB.y += ex * v1.y; accB.z += ex * v1.z; accB.w += ex * v1.w;
    }

    float inv = 1.f / (den + 1e-16f);
    // h = gelu(msg + bv*(deg>0) + s + bs)   (weights sum to 1 folds bv out of the loop)
    float bvs = (deg > 0) ? 1.f : 0.f;
    const float* sp = g_Z + (size_t)warp * 1024 + 768;
    float4 sa = *(const float4*)&sp[lane * 4];
    float4 sb = *(const float4*)&sp[128 + lane * 4];
    float4 bsa = *(const float4*)&bs[lane * 4];
    float4 bsb = *(const float4*)&bs[128 + lane * 4];
    float4 bva = *(const float4*)&bv[lane * 4];
    float4 bvb = *(const float4*)&bv[128 + lane * 4];
    float4 ha, hb;
    {
        float v0 = accA.x * inv + bvs * bva.x + sa.x + bsa.x;
        float v1 = accA.y * inv + bvs * bva.y + sa.y + bsa.y;
        float v2 = accA.z * inv + bvs * bva.z + sa.z + bsa.z;
        float v3 = accA.w * inv + bvs * bva.w + sa.w + bsa.w;
        ha.x = 0.5f * v0 * (1.0f + erff(v0 * 0.70710678118654752f));
        ha.y = 0.5f * v1 * (1.0f + erff(v1 * 0.70710678118654752f));
        ha.z = 0.5f * v2 * (1.0f + erff(v2 * 0.70710678118654752f));
        ha.w = 0.5f * v3 * (1.0f + erff(v3 * 0.70710678118654752f));
        float w0 = accB.x * inv + bvs * bvb.x + sb.x + bsb.x;
        float w1 = accB.y * inv + bvs * bvb.y + sb.y + bsb.y;
        float w2 = accB.z * inv + bvs * bvb.z + sb.z + bsb.z;
        float w3 = accB.w * inv + bvs * bvb.w + sb.w + bsb.w;
        hb.x = 0.5f * w0 * (1.0f + erff(w0 * 0.70710678118654752f));
        hb.y = 0.5f * w1 * (1.0f + erff(w1 * 0.70710678118654752f));
        hb.z = 0.5f * w2 * (1.0f + erff(w2 * 0.70710678118654752f));
        hb.w = 0.5f * w3 * (1.0f + erff(w3 * 0.70710678118654752f));
    }
    *(float4*)&hout[(size_t)warp * 256 + lane * 4] = ha;
    *(float4*)&hout[(size_t)warp * 256 + 128 + lane * 4] = hb;
}

// ---------------- scores: g = tanh(T1+ba)*sigmoid(T2+bb); scores = g @ Wc + bc ----------------
__global__ void scores_kernel(const float* __restrict__ Wc, const float* __restrict__ bc,
                              const float* __restrict__ ba, const float* __restrict__ bb) {
    int warp = (blockIdx.x * blockDim.x + threadIdx.x) >> 5;
    int lane = threadIdx.x & 31;
    if (warp >= N_NODES) return;
    const float* t = g_T + (size_t)warp * 512;
    float acc0 = 0.f, acc1 = 0.f;
    #pragma unroll
    for (int half = 0; half < 2; half++) {
        int c0 = half * 128 + lane * 4;
        float4 t1 = *(const float4*)&t[c0];
        float4 t2 = *(const float4*)&t[256 + c0];
        float4 a4 = *(const float4*)&ba[c0];
        float4 b4 = *(const float4*)&bb[c0];
        float g0 = tanhf(t1.x + a4.x) * (1.f / (1.f + expf(-(t2.x + b4.x))));
        float g1 = tanhf(t1.y + a4.y) * (1.f / (1.f + expf(-(t2.y + b4.y))));
        float g2 = tanhf(t1.z + a4.z) * (1.f / (1.f + expf(-(t2.z + b4.z))));
        float g3 = tanhf(t1.w + a4.w) * (1.f / (1.f + expf(-(t2.w + b4.w))));
        acc0 += g0 * Wc[(c0 + 0) * 2] + g1 * Wc[(c0 + 1) * 2] + g2 * Wc[(c0 + 2) * 2] + g3 * Wc[(c0 + 3) * 2];
        acc1 += g0 * Wc[(c0 + 0) * 2 + 1] + g1 * Wc[(c0 + 1) * 2 + 1] + g2 * Wc[(c0 + 2) * 2 + 1] + g3 * Wc[(c0 + 3) * 2 + 1];
    }
    #pragma unroll
    for (int o = 16; o > 0; o >>= 1) {
        acc0 += __shfl_down_sync(0xffffffffu, acc0, o);
        acc1 += __shfl_down_sync(0xffffffffu, acc1, o);
    }
    if (lane == 0) {
        float s0 = acc0 + bc[0];
        float s1 = acc1 + bc[1];
        g_scores[2 * warp]     = s0;
        g_scores[2 * warp + 1] = s1;
        atomicMax(&g_smax[0], fmapU(s0));
        atomicMax(&g_smax[1], fmapU(s1));
    }
}

// ---------------- softmax denominators over all nodes ----------------
__global__ void sumexp_kernel() {
    float m0 = funmapU(g_smax[0]);
    float m1 = funmapU(g_smax[1]);
    int i = blockIdx.x * blockDim.x + threadIdx.x;
    int stride = gridDim.x * blockDim.x;
    float e0 = 0.f, e1 = 0.f;
    for (int n = i; n < N_NODES; n += stride) {
        e0 += expf(g_scores[2 * n]     - m0);
        e1 += expf(g_scores[2 * n + 1] - m1);
    }
    #pragma unroll
    for (int o = 16; o > 0; o >>= 1) {
        e0 += __shfl_down_sync(0xffffffffu, e0, o);
        e1 += __shfl_down_sync(0xffffffffu, e1, o);
    }
    if ((threadIdx.x & 31) == 0) {
        atomicAdd(&g_ssum[0], e0);
        atomicAdd(&g_ssum[1], e1);
    }
}

// ---------------- finalize: A = attn[:,label]; y = attn^T @ h ----------------
#define CHUNK 128
__global__ __launch_bounds__(256) void finalize_kernel(
    const float* __restrict__ h, const int* __restrict__ label,
    float* __restrict__ y, float* __restrict__ A)
{
    __shared__ float sA0[CHUNK], sA1[CHUNK];
    float m0 = funmapU(g_smax[0]);
    float m1 = funmapU(g_smax[1]);
    float inv0 = 1.f / g_ssum[0];
    float inv1 = 1.f / g_ssum[1];
    int base = blockIdx.x * CHUNK;
    int t = threadIdx.x;
    int lab = label ? *label : 1;
    if (t < CHUNK) {
        int n = base + t;
        if (n < N_NODES) {
            float a0 = expf(g_scores[2 * n]     - m0) * inv0;
            float a1 = expf(g_scores[2 * n + 1] - m1) * inv1;
            sA0[t] = a0;
            sA1[t] = a1;
            A[n] = lab ? a1 : a0;
        } else {
            sA0[t] = 0.f;
            sA1[t] = 0.f;
        }
    }
    __syncthreads();
    float y0 = 0.f, y1 = 0.f;
    int nmax = N_NODES - base;
    if (nmax > CHUNK) nmax = CHUNK;
    for (int j = 0; j < nmax; j++) {
        float hv = h[(size_t)(base + j) * 256 + t];
        y0 += sA0[j] * hv;
        y1 += sA1[j] * hv;
    }
    atomicAdd(&y[t],       y0);
    atomicAdd(&y[256 + t], y1);
}

// ---------------- launch ----------------
extern "C" void kernel_launch(void* const* d_in, const int* in_sizes, int n_in,
                              void* d_out, int out_size)
{
    const float* x  = (const float*)d_in[0];
    const float* Wq = (const float*)d_in[1];
    const float* bq = (const float*)d_in[2];
    const float* Wk = (const float*)d_in[3];
    const float* bk = (const float*)d_in[4];
    const float* Wv = (const float*)d_in[5];
    const float* bv = (const float*)d_in[6];
    const float* Ws = (const float*)d_in[7];
    const float* bs = (const float*)d_in[8];
    const float* Wa = (const float*)d_in[9];
    const float* ba = (const float*)d_in[10];
    const float* Wb = (const float*)d_in[11];
    const float* bb = (const float*)d_in[12];
    const float* Wc = (const float*)d_in[13];
    const float* bc = (const float*)d_in[14];
    const int*   ei = (const int*)d_in[15];
    const int*   lab = (n_in > 16) ? (const int*)d_in[16] : nullptr;

    float* out = (float*)d_out;
    float* y = out;                       // [2, 256]
    float* A = out + 512;                 // [50000]
    float* h = out + 512 + N_NODES;       // [50000, 256]

    float *pZ, *pW1, *pT, *pW2;
    cudaGetSymbolAddress((void**)&pZ,  g_Z);
    cudaGetSymbolAddress((void**)&pW1, g_W1);
    cudaGetSymbolAddress((void**)&pT,  g_T);
    cudaGetSymbolAddress((void**)&pW2, g_W2);

    cudaFuncSetAttribute(gemm_tf32, cudaFuncAttributeMaxDynamicSharedMemorySize, GEMM_SMEM);

    pack1_kernel<<<(L_IN * 1024 + 255) / 256, 256>>>(Wq, Wk, Wv, Ws);
    pack2_kernel<<<(D_HID * 512 + 255) / 256, 256>>>(Wa, Wb);
    init_kernel<<<256, 256>>>(y);

    // CSR build (cheap; overlaps nothing but is only ~40us total)
    count_kernel<<<(N_EDGES + 255) / 256, 256>>>(ei);
    scan_kernel<<<1, 1024>>>();
    fill_kernel<<<(N_EDGES + 255) / 256, 256>>>(ei);

    // Z = x @ [Wq|Wk|Wv|Ws]   (M=50000 padded to 50176, N=1024, K=1024)
    gemm_tf32<<<dim3(1024 / BN, ZROWS / BM), 256, GEMM_SMEM>>>(
        x, pW1, pZ, N_NODES, 1024, 1024);

    // fused single-pass per-node edge softmax + gather + gelu -> h
    edge_fused_kernel<<<(N_NODES * 32 + 255) / 256, 256>>>(bq, bk, bv, bs, h);

    // T = h @ [Wa|Wb]   (M=50000 padded, N=512, K=256)
    gemm_tf32<<<dim3(512 / BN, ZROWS / BM), 256, GEMM_SMEM>>>(
        h, pW2, pT, N_NODES, 512, 256);

    scores_kernel<<<(N_NODES * 32 + 255) / 256, 256>>>(Wc, bc, ba, bb);
    sumexp_kernel<<<256, 256>>>();
    finalize_kernel<<<(N_NODES + CHUNK - 1) / CHUNK, 256>>>(h, lab, y, A);
}

// round 12
// speedup vs baseline: 3.3535x; 1.8872x over previous
#include <cuda_runtime.h>
#include <cuda_fp16.h>
#include <mma.h>
#include <math.h>
#include <stdint.h>

using namespace nvcuda;

#define N_NODES 50000
#define ZROWS   50176          // multiple of 256: guard-free GEMM tiles
#define N_EDGES 800000
#define L_IN    1024
#define D_HID   256

// ---------------- scratch (device globals; no allocation allowed) ----------------
__device__ float  g_Z[(size_t)ZROWS * 1024];    // [q | k | v | s] per node (no bias)
__device__ __half g_Xh[(size_t)ZROWS * 1024];   // x in fp16 (pad rows zero)
__device__ __half g_W1[(size_t)1024 * 1024];    // packed [Wq|Wk|Wv|Ws] as [K][N] fp16
__device__ float  g_T[(size_t)ZROWS * 512];     // [h@Wa | h@Wb] (no bias)
__device__ __half g_Hh[(size_t)ZROWS * 256];    // h in fp16 (pad rows zero)
__device__ __half g_W2[(size_t)256 * 512];      // packed [Wa|Wb] as [K][N] fp16
__device__ float g_scores[N_NODES * 2];
__device__ unsigned g_smax[2];
__device__ float g_ssum[2];
// CSR scratch
__device__ int g_cnt[N_NODES];
__device__ int g_off[N_NODES];
__device__ int g_cur[N_NODES];
__device__ int g_srcs[N_EDGES];

// ---------------- helpers ----------------
__device__ __forceinline__ unsigned fmapU(float f) {
    int i = __float_as_int(f);
    return (i < 0) ? ~((unsigned)i) : (((unsigned)i) | 0x80000000u);
}
__device__ __forceinline__ float funmapU(unsigned u) {
    int i = (u & 0x80000000u) ? (int)(u & 0x7fffffffu) : (int)(~u);
    return __int_as_float(i);
}

// ---------------- pack kernels: [K][N] fp16 (biases folded into consumers) ----------------
__global__ void pack1_kernel(const float* __restrict__ Wq, const float* __restrict__ Wk,
                             const float* __restrict__ Wv, const float* __restrict__ Ws) {
    int i = blockIdx.x * blockDim.x + threadIdx.x;
    if (i < 1024 * 1024) {
        int k = i >> 10, n = i & 1023;
        int m = n >> 8, lc = n & 255;
        const float* W = (m == 0) ? Wq : (m == 1) ? Wk : (m == 2) ? Wv : Ws;
        g_W1[i] = __float2half_rn(W[k * 256 + lc]);
    }
}

__global__ void pack2_kernel(const float* __restrict__ Wa, const float* __restrict__ Wb) {
    int i = blockIdx.x * blockDim.x + threadIdx.x;
    if (i < 256 * 512) {
        int k = i >> 9, n = i & 511;
        int m = n >> 8, lc = n & 255;
        const float* W = (m == 0) ? Wa : Wb;
        g_W2[i] = __float2half_rn(W[k * 256 + lc]);
    }
}

// ---------------- x -> fp16 copy (pad rows zero) ----------------
__global__ void convx_kernel(const float* __restrict__ x) {
    int i = blockIdx.x * blockDim.x + threadIdx.x;     // group of 4 elements
    if (i >= ZROWS * 256) return;
    int row = i >> 8, c = (i & 255) * 4;
    __half2 h01 = __floats2half2_rn(0.f, 0.f), h23 = h01;
    if (row < N_NODES) {
        float4 v = *(const float4*)&x[(size_t)row * 1024 + c];
        h01 = __floats2half2_rn(v.x, v.y);
        h23 = __floats2half2_rn(v.z, v.w);
    }
    uint2 o;
    o.x = *(uint32_t*)&h01;
    o.y = *(uint32_t*)&h23;
    *(uint2*)&g_Xh[(size_t)row * 1024 + c] = o;
}

// ---------------- init ----------------
__global__ void init_kernel(float* __restrict__ y) {
    int i = blockIdx.x * blockDim.x + threadIdx.x;
    int stride = gridDim.x * blockDim.x;
    for (int j = i; j < N_NODES; j += stride) g_cnt[j] = 0;
    // zero fp16 pad rows of h (rows N_NODES..ZROWS)
    const int padElems = (ZROWS - N_NODES) * 256;
    for (int j = i; j < padElems; j += stride)
        g_Hh[(size_t)N_NODES * 256 + j] = __float2half_rn(0.f);
    if (i < 512) y[i] = 0.f;
    if (i < 2) { g_ssum[i] = 0.f; g_smax[i] = 0u; }
}

// ---------------- FP16 GEMM: C[M,N] = A[M,K] @ B[K,N]  (fp32 accum) ----------------
// BM=256, BN=128, BK=64, 3-stage cp.async, 256 threads = 8 warps (4x2), 64x64 each.
#define BM 256
#define BN 128
#define BK 64
#define NSTG 3
#define APITCH (BK + 8)      // 72 halves (144B, 16B-aligned rows)
#define BPITCH (BN + 8)      // 136 halves (272B)
#define ASZ (BM * APITCH)    // halves
#define BSZ (BK * BPITCH)
#define GEMM_SMEM (NSTG * (ASZ + BSZ) * 2)   // 162816 B

__device__ __forceinline__ void cp16(uint32_t s, const void* g) {
    asm volatile("cp.async.cg.shared.global [%0], [%1], 16;" :: "r"(s), "l"(g));
}

__global__ __launch_bounds__(256) void gemm_fp16(
    const __half* __restrict__ A, const __half* __restrict__ B,
    float* __restrict__ C, int ldC, int K)
{
    extern __shared__ __half sm[];
    __half* As = sm;                    // [NSTG][BM][APITCH]
    __half* Bs = sm + NSTG * ASZ;       // [NSTG][BK][BPITCH]
    uint32_t sAs = (uint32_t)__cvta_generic_to_shared(As);
    uint32_t sBs = (uint32_t)__cvta_generic_to_shared(Bs);

    int n0 = blockIdx.x * BN;
    int m0 = blockIdx.y * BM;
    int tid = threadIdx.x;
    int warpId = tid >> 5;
    int wm0 = (warpId & 3) * 64;
    int wn0 = (warpId >> 2) * 64;

    wmma::fragment<wmma::accumulator, 16, 16, 16, float> acc[4][4];
    #pragma unroll
    for (int i = 0; i < 4; i++)
        #pragma unroll
        for (int j = 0; j < 4; j++)
            wmma::fill_fragment(acc[i][j], 0.0f);

    const __half* Ap = A + (size_t)(m0 + tid) * K;   // one row per thread
    const __half* Bp = B + (size_t)(tid >> 2) * ldC + n0;
    int bch = (tid & 3);

    auto loadTile = [&](int buf, int kk) {
        // A: 256 rows, each thread its own row: 8 x 16B = 64 halves
        #pragma unroll
        for (int j = 0; j < 8; j++)
            cp16(sAs + (uint32_t)(buf * ASZ + tid * APITCH + j * 8) * 2, Ap + kk + j * 8);
        // B: 64 rows x 128 halves; row = tid>>2, 4 chunks of 16B per thread
        const __half* bp = Bp + (size_t)kk * ldC;
        #pragma unroll
        for (int j = 0; j < 4; j++) {
            int ch = bch + j * 4;
            cp16(sBs + (uint32_t)(buf * BSZ + (tid >> 2) * BPITCH + ch * 8) * 2, bp + ch * 8);
        }
        asm volatile("cp.async.commit_group;");
    };

    int nT = K / BK;
    loadTile(0, 0);
    loadTile(1, BK);

    for (int t = 0; t < nT; t++) {
        if (t + 2 < nT) {
            loadTile((t + 2) % NSTG, (t + 2) * BK);
            asm volatile("cp.async.wait_group 2;");
        } else if (t + 1 < nT) {
            asm volatile("cp.async.wait_group 1;");
        } else {
            asm volatile("cp.async.wait_group 0;");
        }
        __syncthreads();

        int buf = t % NSTG;
        const __half* Ab = As + buf * ASZ;
        const __half* Bb = Bs + buf * BSZ;
        #pragma unroll
        for (int ks = 0; ks < BK; ks += 16) {
            wmma::fragment<wmma::matrix_a, 16, 16, 16, __half, wmma::row_major> af[4];
            wmma::fragment<wmma::matrix_b, 16, 16, 16, __half, wmma::row_major> bf[4];
            #pragma unroll
            for (int i = 0; i < 4; i++)
                wmma::load_matrix_sync(af[i], &Ab[(wm0 + i * 16) * APITCH + ks], APITCH);
            #pragma unroll
            for (int j = 0; j < 4; j++)
                wmma::load_matrix_sync(bf[j], &Bb[ks * BPITCH + wn0 + j * 16], BPITCH);
            #pragma unroll
            for (int i = 0; i < 4; i++)
                #pragma unroll
                for (int j = 0; j < 4; j++)
                    wmma::mma_sync(acc[i][j], af[i], bf[j], acc[i][j]);
        }
        __syncthreads();
    }

    // direct stores — C rows padded to BM multiples, no guards needed
    #pragma unroll
    for (int i = 0; i < 4; i++)
        #pragma unroll
        for (int j = 0; j < 4; j++)
            wmma::store_matrix_sync(&C[(size_t)(m0 + wm0 + i * 16) * ldC + n0 + wn0 + j * 16],
                                    acc[i][j], ldC, wmma::mem_row_major);
}

// ---------------- CSR build ----------------
__global__ void count_kernel(const int* __restrict__ ei) {
    int i = blockIdx.x * blockDim.x + threadIdx.x;
    if (i < N_EDGES) atomicAdd(&g_cnt[ei[N_EDGES + i]], 1);
}

__global__ __launch_bounds__(1024) void scan_kernel() {
    __shared__ int part[1024];
    const int CH = (N_NODES + 1023) / 1024;
    int t = threadIdx.x;
    int base = t * CH;
    int s = 0;
    for (int j = 0; j < CH; j++) {
        int idx = base + j;
        if (idx < N_NODES) s += g_cnt[idx];
    }
    part[t] = s;
    __syncthreads();
    for (int off = 1; off < 1024; off <<= 1) {
        int v = (t >= off) ? part[t - off] : 0;
        __syncthreads();
        part[t] += v;
        __syncthreads();
    }
    int run = part[t] - s;
    for (int j = 0; j < CH; j++) {
        int idx = base + j;
        if (idx < N_NODES) {
            g_off[idx] = run;
            g_cur[idx] = run;
            run += g_cnt[idx];
        }
    }
}

__global__ void fill_kernel(const int* __restrict__ ei) {
    int i = blockIdx.x * blockDim.x + threadIdx.x;
    if (i >= N_EDGES) return;
    int src = ei[i];
    int dst = ei[N_EDGES + i];
    int pos = atomicAdd(&g_cur[dst], 1);
    g_srcs[pos] = src;
}

// ---------------- fused per-node single-pass edge softmax + gather + gelu ----------------
__device__ __forceinline__ float dot8(const float4& a0, const float4& a1,
                                      const float4& b0, const float4& b1) {
    return a0.x * b0.x + a0.y * b0.y + a0.z * b0.z + a0.w * b0.w
         + a1.x * b1.x + a1.y * b1.y + a1.z * b1.z + a1.w * b1.w;
}

__global__ void edge_fused_kernel(const float* __restrict__ bq, const float* __restrict__ bk,
                                  const float* __restrict__ bv, const float* __restrict__ bs,
                                  float* __restrict__ hout) {
    int warp = (blockIdx.x * blockDim.x + threadIdx.x) >> 5;
    int lane = threadIdx.x & 31;
    if (warp >= N_NODES) return;
    int start = g_off[warp];
    int deg = g_cnt[warp];

    const float* qp = g_Z + (size_t)warp * 1024;
    float4 q0 = *(const float4*)&qp[lane * 4];
    float4 q1 = *(const float4*)&qp[128 + lane * 4];
    {
        float4 bq0 = *(const float4*)&bq[lane * 4];
        float4 bq1 = *(const float4*)&bq[128 + lane * 4];
        q0.x += bq0.x; q0.y += bq0.y; q0.z += bq0.z; q0.w += bq0.w;
        q1.x += bq1.x; q1.y += bq1.y; q1.z += bq1.z; q1.w += bq1.w;
    }
    float dqbk;
    {
        float4 bk0 = *(const float4*)&bk[lane * 4];
        float4 bk1 = *(const float4*)&bk[128 + lane * 4];
        dqbk = dot8(q0, q1, bk0, bk1);
        #pragma unroll
        for (int o = 16; o > 0; o >>= 1) dqbk += __shfl_xor_sync(0xffffffffu, dqbk, o);
    }

    float den = 0.f;
    float4 accA = make_float4(0.f, 0.f, 0.f, 0.f);
    float4 accB = make_float4(0.f, 0.f, 0.f, 0.f);

    int i = 0;
    for (; i + 1 < deg; i += 2) {
        int srcX = g_srcs[start + i];
        int srcY = g_srcs[start + i + 1];
        const float* kvX = g_Z + (size_t)srcX * 1024 + 256;
        const float* kvY = g_Z + (size_t)srcY * 1024 + 256;
        float4 kX0 = *(const float4*)&kvX[lane * 4];
        float4 kX1 = *(const float4*)&kvX[128 + lane * 4];
        float4 kY0 = *(const float4*)&kvY[lane * 4];
        float4 kY1 = *(const float4*)&kvY[128 + lane * 4];
        float sX = dot8(q0, q1, kX0, kX1);
        float sY = dot8(q0, q1, kY0, kY1);
        #pragma unroll
        for (int o = 16; o > 0; o >>= 1) {
            sX += __shfl_xor_sync(0xffffffffu, sX, o);
            sY += __shfl_xor_sync(0xffffffffu, sY, o);
        }
        float exX = expf((sX + dqbk) * 0.0625f);   // max-shift skipped: identical
        float exY = expf((sY + dqbk) * 0.0625f);
        den += exX + exY;
        float4 vX0 = *(const float4*)&kvX[256 + lane * 4];
        float4 vX1 = *(const float4*)&kvX[384 + lane * 4];
        float4 vY0 = *(const float4*)&kvY[256 + lane * 4];
        float4 vY1 = *(const float4*)&kvY[384 + lane * 4];
        accA.x += exX * vX0.x + exY * vY0.x;
        accA.y += exX * vX0.y + exY * vY0.y;
        accA.z += exX * vX0.z + exY * vY0.z;
        accA.w += exX * vX0.w + exY * vY0.w;
        accB.x += exX * vX1.x + exY * vY1.x;
        accB.y += exX * vX1.y + exY * vY1.y;
        accB.z += exX * vX1.z + exY * vY1.z;
        accB.w += exX * vX1.w + exY * vY1.w;
    }
    if (i < deg) {
        int src = g_srcs[start + i];
        const float* kv = g_Z + (size_t)src * 1024 + 256;
        float4 k0 = *(const float4*)&kv[lane * 4];
        float4 k1 = *(const float4*)&kv[128 + lane * 4];
        float s = dot8(q0, q1, k0, k1);
        #pragma unroll
        for (int o = 16; o > 0; o >>= 1) s += __shfl_xor_sync(0xffffffffu, s, o);
        float ex = expf((s + dqbk) * 0.0625f);
        den += ex;
        float4 v0 = *(const float4*)&kv[256 + lane * 4];
        float4 v1 = *(const float4*)&kv[384 + lane * 4];
        accA.x += ex * v0.x; accA.y += ex * v0.y; accA.z += ex * v0.z; accA.w += ex * v0.w;
        accB.x += ex * v1.x; accB.y += ex * v1.y; accB.z += ex * v1.z; accB.w += ex * v1.w;
    }

    float inv = 1.f / (den + 1e-16f);
    float bvs = (deg > 0) ? 1.f : 0.f;
    const float* sp = g_Z + (size_t)warp * 1024 + 768;
    float4 sa = *(const float4*)&sp[lane * 4];
    float4 sb = *(const float4*)&sp[128 + lane * 4];
    float4 bsa = *(const float4*)&bs[lane * 4];
    float4 bsb = *(const float4*)&bs[128 + lane * 4];
    float4 bva = *(const float4*)&bv[lane * 4];
    float4 bvb = *(const float4*)&bv[128 + lane * 4];
    float4 ha, hb;
    {
        float v0 = accA.x * inv + bvs * bva.x + sa.x + bsa.x;
        float v1 = accA.y * inv + bvs * bva.y + sa.y + bsa.y;
        float v2 = accA.z * inv + bvs * bva.z + sa.z + bsa.z;
        float v3 = accA.w * inv + bvs * bva.w + sa.w + bsa.w;
        ha.x = 0.5f * v0 * (1.0f + erff(v0 * 0.70710678118654752f));
        ha.y = 0.5f * v1 * (1.0f + erff(v1 * 0.70710678118654752f));
        ha.z = 0.5f * v2 * (1.0f + erff(v2 * 0.70710678118654752f));
        ha.w = 0.5f * v3 * (1.0f + erff(v3 * 0.70710678118654752f));
        float w0 = accB.x * inv + bvs * bvb.x + sb.x + bsb.x;
        float w1 = accB.y * inv + bvs * bvb.y + sb.y + bsb.y;
        float w2 = accB.z * inv + bvs * bvb.z + sb.z + bsb.z;
        float w3 = accB.w * inv + bvs * bvb.w + sb.w + bsb.w;
        hb.x = 0.5f * w0 * (1.0f + erff(w0 * 0.70710678118654752f));
        hb.y = 0.5f * w1 * (1.0f + erff(w1 * 0.70710678118654752f));
        hb.z = 0.5f * w2 * (1.0f + erff(w2 * 0.70710678118654752f));
        hb.w = 0.5f * w3 * (1.0f + erff(w3 * 0.70710678118654752f));
    }
    *(float4*)&hout[(size_t)warp * 256 + lane * 4] = ha;
    *(float4*)&hout[(size_t)warp * 256 + 128 + lane * 4] = hb;
    // fp16 copy for GEMM2
    {
        __half2 p0 = __floats2half2_rn(ha.x, ha.y);
        __half2 p1 = __floats2half2_rn(ha.z, ha.w);
        uint2 oa; oa.x = *(uint32_t*)&p0; oa.y = *(uint32_t*)&p1;
        *(uint2*)&g_Hh[(size_t)warp * 256 + lane * 4] = oa;
        __half2 p2 = __floats2half2_rn(hb.x, hb.y);
        __half2 p3 = __floats2half2_rn(hb.z, hb.w);
        uint2 ob; ob.x = *(uint32_t*)&p2; ob.y = *(uint32_t*)&p3;
        *(uint2*)&g_Hh[(size_t)warp * 256 + 128 + lane * 4] = ob;
    }
}

// ---------------- scores: g = tanh(T1+ba)*sigmoid(T2+bb); scores = g @ Wc + bc ----------------
__global__ void scores_kernel(const float* __restrict__ Wc, const float* __restrict__ bc,
                              const float* __restrict__ ba, const float* __restrict__ bb) {
    int warp = (blockIdx.x * blockDim.x + threadIdx.x) >> 5;
    int lane = threadIdx.x & 31;
    if (warp >= N_NODES) return;
    const float* t = g_T + (size_t)warp * 512;
    float acc0 = 0.f, acc1 = 0.f;
    #pragma unroll
    for (int half = 0; half < 2; half++) {
        int c0 = half * 128 + lane * 4;
        float4 t1 = *(const float4*)&t[c0];
        float4 t2 = *(const float4*)&t[256 + c0];
        float4 a4 = *(const float4*)&ba[c0];
        float4 b4 = *(const float4*)&bb[c0];
        float g0 = tanhf(t1.x + a4.x) * (1.f / (1.f + expf(-(t2.x + b4.x))));
        float g1 = tanhf(t1.y + a4.y) * (1.f / (1.f + expf(-(t2.y + b4.y))));
        float g2 = tanhf(t1.z + a4.z) * (1.f / (1.f + expf(-(t2.z + b4.z))));
        float g3 = tanhf(t1.w + a4.w) * (1.f / (1.f + expf(-(t2.w + b4.w))));
        acc0 += g0 * Wc[(c0 + 0) * 2] + g1 * Wc[(c0 + 1) * 2] + g2 * Wc[(c0 + 2) * 2] + g3 * Wc[(c0 + 3) * 2];
        acc1 += g0 * Wc[(c0 + 0) * 2 + 1] + g1 * Wc[(c0 + 1) * 2 + 1] + g2 * Wc[(c0 + 2) * 2 + 1] + g3 * Wc[(c0 + 3) * 2 + 1];
    }
    #pragma unroll
    for (int o = 16; o > 0; o >>= 1) {
        acc0 += __shfl_down_sync(0xffffffffu, acc0, o);
        acc1 += __shfl_down_sync(0xffffffffu, acc1, o);
    }
    if (lane == 0) {
        float s0 = acc0 + bc[0];
        float s1 = acc1 + bc[1];
        g_scores[2 * warp]     = s0;
        g_scores[2 * warp + 1] = s1;
        atomicMax(&g_smax[0], fmapU(s0));
        atomicMax(&g_smax[1], fmapU(s1));
    }
}

// ---------------- softmax denominators over all nodes ----------------
__global__ void sumexp_kernel() {
    float m0 = funmapU(g_smax[0]);
    float m1 = funmapU(g_smax[1]);
    int i = blockIdx.x * blockDim.x + threadIdx.x;
    int stride = gridDim.x * blockDim.x;
    float e0 = 0.f, e1 = 0.f;
    for (int n = i; n < N_NODES; n += stride) {
        e0 += expf(g_scores[2 * n]     - m0);
        e1 += expf(g_scores[2 * n + 1] - m1);
    }
    #pragma unroll
    for (int o = 16; o > 0; o >>= 1) {
        e0 += __shfl_down_sync(0xffffffffu, e0, o);
        e1 += __shfl_down_sync(0xffffffffu, e1, o);
    }
    if ((threadIdx.x & 31) == 0) {
        atomicAdd(&g_ssum[0], e0);
        atomicAdd(&g_ssum[1], e1);
    }
}

// ---------------- finalize: A = attn[:,label]; y = attn^T @ h ----------------
#define CHUNK 128
__global__ __launch_bounds__(256) void finalize_kernel(
    const float* __restrict__ h, const int* __restrict__ label,
    float* __restrict__ y, float* __restrict__ A)
{
    __shared__ float sA0[CHUNK], sA1[CHUNK];
    float m0 = funmapU(g_smax[0]);
    float m1 = funmapU(g_smax[1]);
    float inv0 = 1.f / g_ssum[0];
    float inv1 = 1.f / g_ssum[1];
    int base = blockIdx.x * CHUNK;
    int t = threadIdx.x;
    int lab = label ? *label : 1;
    if (t < CHUNK) {
        int n = base + t;
        if (n < N_NODES) {
            float a0 = expf(g_scores[2 * n]     - m0) * inv0;
            float a1 = expf(g_scores[2 * n + 1] - m1) * inv1;
            sA0[t] = a0;
            sA1[t] = a1;
            A[n] = lab ? a1 : a0;
        } else {
            sA0[t] = 0.f;
            sA1[t] = 0.f;
        }
    }
    __syncthreads();
    float y0 = 0.f, y1 = 0.f;
    int nmax = N_NODES - base;
    if (nmax > CHUNK) nmax = CHUNK;
    for (int j = 0; j < nmax; j++) {
        float hv = h[(size_t)(base + j) * 256 + t];
        y0 += sA0[j] * hv;
        y1 += sA1[j] * hv;
    }
    atomicAdd(&y[t],       y0);
    atomicAdd(&y[256 + t], y1);
}

// ---------------- launch ----------------
extern "C" void kernel_launch(void* const* d_in, const int* in_sizes, int n_in,
                              void* d_out, int out_size)
{
    const float* x  = (const float*)d_in[0];
    const float* Wq = (const float*)d_in[1];
    const float* bq = (const float*)d_in[2];
    const float* Wk = (const float*)d_in[3];
    const float* bk = (const float*)d_in[4];
    const float* Wv = (const float*)d_in[5];
    const float* bv = (const float*)d_in[6];
    const float* Ws = (const float*)d_in[7];
    const float* bs = (const float*)d_in[8];
    const float* Wa = (const float*)d_in[9];
    const float* ba = (const float*)d_in[10];
    const float* Wb = (const float*)d_in[11];
    const float* bb = (const float*)d_in[12];
    const float* Wc = (const float*)d_in[13];
    const float* bc = (const float*)d_in[14];
    const int*   ei = (const int*)d_in[15];
    const int*   lab = (n_in > 16) ? (const int*)d_in[16] : nullptr;

    float* out = (float*)d_out;
    float* y = out;                       // [2, 256]
    float* A = out + 512;                 // [50000]
    float* h = out + 512 + N_NODES;       // [50000, 256]

    __half *pXh, *pW1, *pHh, *pW2;
    float *pZ, *pT;
    cudaGetSymbolAddress((void**)&pXh, g_Xh);
    cudaGetSymbolAddress((void**)&pW1, g_W1);
    cudaGetSymbolAddress((void**)&pZ,  g_Z);
    cudaGetSymbolAddress((void**)&pT,  g_T);
    cudaGetSymbolAddress((void**)&pW2, g_W2);
    cudaGetSymbolAddress((void**)&pHh, g_Hh);

    cudaFuncSetAttribute(gemm_fp16, cudaFuncAttributeMaxDynamicSharedMemorySize, GEMM_SMEM);

    convx_kernel<<<(ZROWS * 256 + 255) / 256, 256>>>(x);
    pack1_kernel<<<(1024 * 1024 + 255) / 256, 256>>>(Wq, Wk, Wv, Ws);
    pack2_kernel<<<(256 * 512 + 255) / 256, 256>>>(Wa, Wb);
    init_kernel<<<256, 256>>>(y);

    // CSR build
    count_kernel<<<(N_EDGES + 255) / 256, 256>>>(ei);
    scan_kernel<<<1, 1024>>>();
    fill_kernel<<<(N_EDGES + 255) / 256, 256>>>(ei);

    // Z = xh @ W1  (fp16 HMMA, fp32 accum; M=50176, N=1024, K=1024)
    gemm_fp16<<<dim3(1024 / BN, ZROWS / BM), 256, GEMM_SMEM>>>(pXh, pW1, pZ, 1024, 1024);

    // fused single-pass per-node edge softmax + gather + gelu -> h (+ fp16 copy)
    edge_fused_kernel<<<(N_NODES * 32 + 255) / 256, 256>>>(bq, bk, bv, bs, h);

    // T = hh @ W2  (M=50176, N=512, K=256)
    gemm_fp16<<<dim3(512 / BN, ZROWS / BM), 256, GEMM_SMEM>>>(pHh, pW2, pT, 512, 256);

    scores_kernel<<<(N_NODES * 32 + 255) / 256, 256>>>(Wc, bc, ba, bb);
    sumexp_kernel<<<256, 256>>>();
    finalize_kernel<<<(N_NODES + CHUNK - 1) / CHUNK, 256>>>(h, lab, y, A);
}

// round 15
// speedup vs baseline: 3.5511x; 1.0589x over previous
#include <cuda_runtime.h>
#include <cuda_fp16.h>
#include <mma.h>
#include <math.h>
#include <stdint.h>

using namespace nvcuda;

#define N_NODES 50000
#define ZROWS   50176          // multiple of 256: guard-free GEMM tiles
#define N_EDGES 800000
#define L_IN    1024
#define D_HID   256

// ---------------- scratch (device globals; no allocation allowed) ----------------
__device__ float  g_Z[(size_t)ZROWS * 1024];    // only cols 768..1023 (s) are written/read fp32
__device__ __half g_KVh[(size_t)ZROWS * 768];   // [q | k | v] fp16, compact stride 768
__device__ __half g_Xh[(size_t)ZROWS * 1024];   // x in fp16 (pad rows zero)
__device__ __half g_W1[(size_t)1024 * 1024];    // packed [Wq|Wk|Wv|Ws] as [K][N] fp16
__device__ float  g_T[(size_t)ZROWS * 512];     // [h@Wa | h@Wb] (no bias)
__device__ __half g_Hh[(size_t)ZROWS * 256];    // h in fp16 (pad rows zero)
__device__ __half g_W2[(size_t)256 * 512];      // packed [Wa|Wb] as [K][N] fp16
__device__ float g_scores[N_NODES * 2];
__device__ unsigned g_smax[2];
__device__ float g_ssum[2];
// CSR scratch
__device__ int g_cnt[N_NODES];
__device__ int g_off[N_NODES];
__device__ int g_cur[N_NODES];
__device__ int g_srcs[N_EDGES];

// ---------------- helpers ----------------
__device__ __forceinline__ unsigned fmapU(float f) {
    int i = __float_as_int(f);
    return (i < 0) ? ~((unsigned)i) : (((unsigned)i) | 0x80000000u);
}
__device__ __forceinline__ float funmapU(unsigned u) {
    int i = (u & 0x80000000u) ? (int)(u & 0x7fffffffu) : (int)(~u);
    return __int_as_float(i);
}

// ---------------- pack kernels: [K][N] fp16 (biases folded into consumers) ----------------
__global__ void pack1_kernel(const float* __restrict__ Wq, const float* __restrict__ Wk,
                             const float* __restrict__ Wv, const float* __restrict__ Ws) {
    int i = blockIdx.x * blockDim.x + threadIdx.x;
    if (i < 1024 * 1024) {
        int k = i >> 10, n = i & 1023;
        int m = n >> 8, lc = n & 255;
        const float* W = (m == 0) ? Wq : (m == 1) ? Wk : (m == 2) ? Wv : Ws;
        g_W1[i] = __float2half_rn(W[k * 256 + lc]);
    }
}

__global__ void pack2_kernel(const float* __restrict__ Wa, const float* __restrict__ Wb) {
    int i = blockIdx.x * blockDim.x + threadIdx.x;
    if (i < 256 * 512) {
        int k = i >> 9, n = i & 511;
        int m = n >> 8, lc = n & 255;
        const float* W = (m == 0) ? Wa : Wb;
        g_W2[i] = __float2half_rn(W[k * 256 + lc]);
    }
}

// ---------------- x -> fp16 copy (pad rows zero) ----------------
__global__ void convx_kernel(const float* __restrict__ x) {
    int i = blockIdx.x * blockDim.x + threadIdx.x;     // group of 4 elements
    if (i >= ZROWS * 256) return;
    int row = i >> 8, c = (i & 255) * 4;
    __half2 h01 = __floats2half2_rn(0.f, 0.f), h23 = h01;
    if (row < N_NODES) {
        float4 v = *(const float4*)&x[(size_t)row * 1024 + c];
        h01 = __floats2half2_rn(v.x, v.y);
        h23 = __floats2half2_rn(v.z, v.w);
    }
    uint2 o;
    o.x = *(uint32_t*)&h01;
    o.y = *(uint32_t*)&h23;
    *(uint2*)&g_Xh[(size_t)row * 1024 + c] = o;
}

// ---------------- init ----------------
__global__ void init_kernel(float* __restrict__ y) {
    int i = blockIdx.x * blockDim.x + threadIdx.x;
    int stride = gridDim.x * blockDim.x;
    for (int j = i; j < N_NODES; j += stride) g_cnt[j] = 0;
    // zero fp16 pad rows of h (rows N_NODES..ZROWS)
    const int padElems = (ZROWS - N_NODES) * 256;
    for (int j = i; j < padElems; j += stride)
        g_Hh[(size_t)N_NODES * 256 + j] = __float2half_rn(0.f);
    if (i < 512) y[i] = 0.f;
    if (i < 2) { g_ssum[i] = 0.f; g_smax[i] = 0u; }
}

// ---------------- FP16 GEMM: C[M,N] = A[M,K] @ B[K,N]  (fp32 accum) ----------------
// BM=256, BN=128, BK=64, 3-stage cp.async, 256 threads = 8 warps (4x2), 64x64 each.
// Epilogue: tiles with n0 < chLimit are stored fp16-only into Ch (stride chLimit);
// remaining tiles stored fp32 into C. Ch==nullptr => all tiles fp32.
#define BM 256
#define BN 128
#define BK 64
#define NSTG 3
#define APITCH (BK + 8)      // 72 halves (144B, 16B-aligned rows)
#define BPITCH (BN + 8)      // 136 halves (272B)
#define ASZ (BM * APITCH)    // halves
#define BSZ (BK * BPITCH)
#define GEMM_SMEM (NSTG * (ASZ + BSZ) * 2)   // 162816 B

__device__ __forceinline__ void cp16(uint32_t s, const void* g) {
    asm volatile("cp.async.cg.shared.global [%0], [%1], 16;" :: "r"(s), "l"(g));
}

__global__ __launch_bounds__(256) void gemm_fp16(
    const __half* __restrict__ A, const __half* __restrict__ B,
    float* __restrict__ C, __half* __restrict__ Ch,
    int ldC, int chLimit, int K)
{
    extern __shared__ __half sm[];
    __half* As = sm;                    // [NSTG][BM][APITCH]
    __half* Bs = sm + NSTG * ASZ;       // [NSTG][BK][BPITCH]
    uint32_t sAs = (uint32_t)__cvta_generic_to_shared(As);
    uint32_t sBs = (uint32_t)__cvta_generic_to_shared(Bs);

    int n0 = blockIdx.x * BN;
    int m0 = blockIdx.y * BM;
    int tid = threadIdx.x;
    int warpId = tid >> 5;
    int lane = tid & 31;
    int wm0 = (warpId & 3) * 64;
    int wn0 = (warpId >> 2) * 64;

    wmma::fragment<wmma::accumulator, 16, 16, 16, float> acc[4][4];
    #pragma unroll
    for (int i = 0; i < 4; i++)
        #pragma unroll
        for (int j = 0; j < 4; j++)
            wmma::fill_fragment(acc[i][j], 0.0f);

    const __half* Ap = A + (size_t)(m0 + tid) * K;   // one row per thread
    const __half* Bp = B + (size_t)(tid >> 2) * ldC + n0;
    int bch = (tid & 3);

    auto loadTile = [&](int buf, int kk) {
        #pragma unroll
        for (int j = 0; j < 8; j++)
            cp16(sAs + (uint32_t)(buf * ASZ + tid * APITCH + j * 8) * 2, Ap + kk + j * 8);
        const __half* bp = Bp + (size_t)kk * ldC;
        #pragma unroll
        for (int j = 0; j < 4; j++) {
            int ch = bch + j * 4;
            cp16(sBs + (uint32_t)(buf * BSZ + (tid >> 2) * BPITCH + ch * 8) * 2, bp + ch * 8);
        }
        asm volatile("cp.async.commit_group;");
    };

    int nT = K / BK;
    loadTile(0, 0);
    loadTile(1, BK);

    for (int t = 0; t < nT; t++) {
        if (t + 2 < nT) {
            loadTile((t + 2) % NSTG, (t + 2) * BK);
            asm volatile("cp.async.wait_group 2;");
        } else if (t + 1 < nT) {
            asm volatile("cp.async.wait_group 1;");
        } else {
            asm volatile("cp.async.wait_group 0;");
        }
        __syncthreads();

        int buf = t % NSTG;
        const __half* Ab = As + buf * ASZ;
        const __half* Bb = Bs + buf * BSZ;
        #pragma unroll
        for (int ks = 0; ks < BK; ks += 16) {
            wmma::fragment<wmma::matrix_a, 16, 16, 16, __half, wmma::row_major> af[4];
            wmma::fragment<wmma::matrix_b, 16, 16, 16, __half, wmma::row_major> bf[4];
            #pragma unroll
            for (int i = 0; i < 4; i++)
                wmma::load_matrix_sync(af[i], &Ab[(wm0 + i * 16) * APITCH + ks], APITCH);
            #pragma unroll
            for (int j = 0; j < 4; j++)
                wmma::load_matrix_sync(bf[j], &Bb[ks * BPITCH + wn0 + j * 16], BPITCH);
            #pragma unroll
            for (int i = 0; i < 4; i++)
                #pragma unroll
                for (int j = 0; j < 4; j++)
                    wmma::mma_sync(acc[i][j], af[i], bf[j], acc[i][j]);
        }
        __syncthreads();
    }

    bool toH = (Ch != nullptr) && (n0 < chLimit);
    if (toH) {
        // per-warp 16x16 fp32 staging strip -> fp16 packed stores (stride chLimit)
        __shared__ float strip[8][16 * 24];
        #pragma unroll
        for (int i = 0; i < 4; i++)
            #pragma unroll
            for (int j = 0; j < 4; j++) {
                wmma::store_matrix_sync(&strip[warpId][0], acc[i][j], 24, wmma::mem_row_major);
                __syncwarp();
                int r = lane >> 1, c0 = (lane & 1) * 8;
                int grow = m0 + wm0 + i * 16 + r;
                int gcol = n0 + wn0 + j * 16 + c0;
                float* sp = &strip[warpId][r * 24 + c0];
                __half2 p0 = __floats2half2_rn(sp[0], sp[1]);
                __half2 p1 = __floats2half2_rn(sp[2], sp[3]);
                __half2 p2 = __floats2half2_rn(sp[4], sp[5]);
                __half2 p3 = __floats2half2_rn(sp[6], sp[7]);
                uint4 pk;
                pk.x = *(uint32_t*)&p0; pk.y = *(uint32_t*)&p1;
                pk.z = *(uint32_t*)&p2; pk.w = *(uint32_t*)&p3;
                *(uint4*)&Ch[(size_t)grow * chLimit + gcol] = pk;
                __syncwarp();
            }
    } else {
        #pragma unroll
        for (int i = 0; i < 4; i++)
            #pragma unroll
            for (int j = 0; j < 4; j++)
                wmma::store_matrix_sync(&C[(size_t)(m0 + wm0 + i * 16) * ldC + n0 + wn0 + j * 16],
                                        acc[i][j], ldC, wmma::mem_row_major);
    }
}

// ---------------- CSR build ----------------
__global__ void count_kernel(const int* __restrict__ ei) {
    int i = blockIdx.x * blockDim.x + threadIdx.x;
    if (i < N_EDGES) atomicAdd(&g_cnt[ei[N_EDGES + i]], 1);
}

__global__ __launch_bounds__(1024) void scan_kernel() {
    __shared__ int part[1024];
    const int CH = (N_NODES + 1023) / 1024;
    int t = threadIdx.x;
    int base = t * CH;
    int s = 0;
    for (int j = 0; j < CH; j++) {
        int idx = base + j;
        if (idx < N_NODES) s += g_cnt[idx];
    }
    part[t] = s;
    __syncthreads();
    for (int off = 1; off < 1024; off <<= 1) {
        int v = (t >= off) ? part[t - off] : 0;
        __syncthreads();
        part[t] += v;
        __syncthreads();
    }
    int run = part[t] - s;
    for (int j = 0; j < CH; j++) {
        int idx = base + j;
        if (idx < N_NODES) {
            g_off[idx] = run;
            g_cur[idx] = run;
            run += g_cnt[idx];
        }
    }
}

__global__ void fill_kernel(const int* __restrict__ ei) {
    int i = blockIdx.x * blockDim.x + threadIdx.x;
    if (i >= N_EDGES) return;
    int src = ei[i];
    int dst = ei[N_EDGES + i];
    int pos = atomicAdd(&g_cur[dst], 1);
    g_srcs[pos] = src;
}

// ---------------- fused per-node single-pass edge softmax + gather + gelu ----------------
// warp per node; q/k/v in fp16 (g_KVh, stride 768: q@0, k@256, v@512).
// lane owns cols lane*8..lane*8+7.
__device__ __forceinline__ void h8tof(const uint4& u, float* f) {
    __half2 a = *(__half2*)&u.x, b = *(__half2*)&u.y;
    __half2 c = *(__half2*)&u.z, d = *(__half2*)&u.w;
    float2 fa = __half22float2(a), fb = __half22float2(b);
    float2 fc = __half22float2(c), fd = __half22float2(d);
    f[0] = fa.x; f[1] = fa.y; f[2] = fb.x; f[3] = fb.y;
    f[4] = fc.x; f[5] = fc.y; f[6] = fd.x; f[7] = fd.y;
}

__global__ void edge_fused_kernel(const float* __restrict__ bq, const float* __restrict__ bk,
                                  const float* __restrict__ bv, const float* __restrict__ bs,
                                  float* __restrict__ hout) {
    int warp = (blockIdx.x * blockDim.x + threadIdx.x) >> 5;
    int lane = threadIdx.x & 31;
    if (warp >= N_NODES) return;
    int start = g_off[warp];
    int deg = g_cnt[warp];
    int c8 = lane * 8;

    // q (fp16) + bq (fp32)
    float q[8];
    {
        uint4 qh = *(const uint4*)&g_KVh[(size_t)warp * 768 + c8];
        h8tof(qh, q);
        float4 b0 = *(const float4*)&bq[c8];
        float4 b1 = *(const float4*)&bq[c8 + 4];
        q[0] += b0.x; q[1] += b0.y; q[2] += b0.z; q[3] += b0.w;
        q[4] += b1.x; q[5] += b1.y; q[6] += b1.z; q[7] += b1.w;
    }
    // per-node constant: (q+bq)·bk
    float dqbk;
    {
        float4 b0 = *(const float4*)&bk[c8];
        float4 b1 = *(const float4*)&bk[c8 + 4];
        dqbk = q[0] * b0.x + q[1] * b0.y + q[2] * b0.z + q[3] * b0.w
             + q[4] * b1.x + q[5] * b1.y + q[6] * b1.z + q[7] * b1.w;
        #pragma unroll
        for (int o = 16; o > 0; o >>= 1) dqbk += __shfl_xor_sync(0xffffffffu, dqbk, o);
    }

    float den = 0.f;
    float acc[8];
    #pragma unroll
    for (int j = 0; j < 8; j++) acc[j] = 0.f;

    int i = 0;
    for (; i + 1 < deg; i += 2) {
        const __half* kvX = g_KVh + (size_t)g_srcs[start + i] * 768 + 256;
        const __half* kvY = g_KVh + (size_t)g_srcs[start + i + 1] * 768 + 256;
        uint4 khX = *(const uint4*)&kvX[c8];
        uint4 khY = *(const uint4*)&kvY[c8];
        float kX[8], kY[8];
        h8tof(khX, kX);
        h8tof(khY, kY);
        float sX = 0.f, sY = 0.f;
        #pragma unroll
        for (int j = 0; j < 8; j++) { sX += q[j] * kX[j]; sY += q[j] * kY[j]; }
        #pragma unroll
        for (int o = 16; o > 0; o >>= 1) {
            sX += __shfl_xor_sync(0xffffffffu, sX, o);
            sY += __shfl_xor_sync(0xffffffffu, sY, o);
        }
        float exX = expf((sX + dqbk) * 0.0625f);   // max-shift skipped: identical
        float exY = expf((sY + dqbk) * 0.0625f);
        den += exX + exY;
        uint4 vhX = *(const uint4*)&kvX[256 + c8];
        uint4 vhY = *(const uint4*)&kvY[256 + c8];
        float vX[8], vY[8];
        h8tof(vhX, vX);
        h8tof(vhY, vY);
        #pragma unroll
        for (int j = 0; j < 8; j++) acc[j] += exX * vX[j] + exY * vY[j];
    }
    if (i < deg) {
        const __half* kv = g_KVh + (size_t)g_srcs[start + i] * 768 + 256;
        uint4 kh = *(const uint4*)&kv[c8];
        float k[8];
        h8tof(kh, k);
        float s = 0.f;
        #pragma unroll
        for (int j = 0; j < 8; j++) s += q[j] * k[j];
        #pragma unroll
        for (int o = 16; o > 0; o >>= 1) s += __shfl_xor_sync(0xffffffffu, s, o);
        float ex = expf((s + dqbk) * 0.0625f);
        den += ex;
        uint4 vh = *(const uint4*)&kv[256 + c8];
        float v[8];
        h8tof(vh, v);
        #pragma unroll
        for (int j = 0; j < 8; j++) acc[j] += ex * v[j];
    }

    float inv = 1.f / (den + 1e-16f);
    float bvs = (deg > 0) ? 1.f : 0.f;
    const float* sp = g_Z + (size_t)warp * 1024 + 768;
    float hv[8];
    {
        float4 s0 = *(const float4*)&sp[c8];
        float4 s1 = *(const float4*)&sp[c8 + 4];
        float4 bs0 = *(const float4*)&bs[c8];
        float4 bs1 = *(const float4*)&bs[c8 + 4];
        float4 bv0 = *(const float4*)&bv[c8];
        float4 bv1 = *(const float4*)&bv[c8 + 4];
        float base[8] = { s0.x + bs0.x + bvs * bv0.x, s0.y + bs0.y + bvs * bv0.y,
                          s0.z + bs0.z + bvs * bv0.z, s0.w + bs0.w + bvs * bv0.w,
                          s1.x + bs1.x + bvs * bv1.x, s1.y + bs1.y + bvs * bv1.y,
                          s1.z + bs1.z + bvs * bv1.z, s1.w + bs1.w + bvs * bv1.w };
        #pragma unroll
        for (int j = 0; j < 8; j++) {
            float u = acc[j] * inv + base[j];
            hv[j] = 0.5f * u * (1.0f + erff(u * 0.70710678118654752f));
        }
    }
    float4 o0 = make_float4(hv[0], hv[1], hv[2], hv[3]);
    float4 o1 = make_float4(hv[4], hv[5], hv[6], hv[7]);
    *(float4*)&hout[(size_t)warp * 256 + c8] = o0;
    *(float4*)&hout[(size_t)warp * 256 + c8 + 4] = o1;
    // fp16 copy for GEMM2
    {
        __half2 p0 = __floats2half2_rn(hv[0], hv[1]);
        __half2 p1 = __floats2half2_rn(hv[2], hv[3]);
        __half2 p2 = __floats2half2_rn(hv[4], hv[5]);
        __half2 p3 = __floats2half2_rn(hv[6], hv[7]);
        uint4 pk;
        pk.x = *(uint32_t*)&p0; pk.y = *(uint32_t*)&p1;
        pk.z = *(uint32_t*)&p2; pk.w = *(uint32_t*)&p3;
        *(uint4*)&g_Hh[(size_t)warp * 256 + c8] = pk;
    }
}

// ---------------- scores: g = tanh(T1+ba)*sigmoid(T2+bb); scores = g @ Wc + bc ----------------
__global__ void scores_kernel(const float* __restrict__ Wc, const float* __restrict__ bc,
                              const float* __restrict__ ba, const float* __restrict__ bb) {
    int warp = (blockIdx.x * blockDim.x + threadIdx.x) >> 5;
    int lane = threadIdx.x & 31;
    if (warp >= N_NODES) return;
    const float* t = g_T + (size_t)warp * 512;
    float acc0 = 0.f, acc1 = 0.f;
    #pragma unroll
    for (int half = 0; half < 2; half++) {
        int c0 = half * 128 + lane * 4;
        float4 t1 = *(const float4*)&t[c0];
        float4 t2 = *(const float4*)&t[256 + c0];
        float4 a4 = *(const float4*)&ba[c0];
        float4 b4 = *(const float4*)&bb[c0];
        float g0 = tanhf(t1.x + a4.x) * (1.f / (1.f + expf(-(t2.x + b4.x))));
        float g1 = tanhf(t1.y + a4.y) * (1.f / (1.f + expf(-(t2.y + b4.y))));
        float g2 = tanhf(t1.z + a4.z) * (1.f / (1.f + expf(-(t2.z + b4.z))));
        float g3 = tanhf(t1.w + a4.w) * (1.f / (1.f + expf(-(t2.w + b4.w))));
        acc0 += g0 * Wc[(c0 + 0) * 2] + g1 * Wc[(c0 + 1) * 2] + g2 * Wc[(c0 + 2) * 2] + g3 * Wc[(c0 + 3) * 2];
        acc1 += g0 * Wc[(c0 + 0) * 2 + 1] + g1 * Wc[(c0 + 1) * 2 + 1] + g2 * Wc[(c0 + 2) * 2 + 1] + g3 * Wc[(c0 + 3) * 2 + 1];
    }
    #pragma unroll
    for (int o = 16; o > 0; o >>= 1) {
        acc0 += __shfl_down_sync(0xffffffffu, acc0, o);
        acc1 += __shfl_down_sync(0xffffffffu, acc1, o);
    }
    if (lane == 0) {
        float s0 = acc0 + bc[0];
        float s1 = acc1 + bc[1];
        g_scores[2 * warp]     = s0;
        g_scores[2 * warp + 1] = s1;
        atomicMax(&g_smax[0], fmapU(s0));
        atomicMax(&g_smax[1], fmapU(s1));
    }
}

// ---------------- softmax denominators over all nodes ----------------
__global__ void sumexp_kernel() {
    float m0 = funmapU(g_smax[0]);
    float m1 = funmapU(g_smax[1]);
    int i = blockIdx.x * blockDim.x + threadIdx.x;
    int stride = gridDim.x * blockDim.x;
    float e0 = 0.f, e1 = 0.f;
    for (int n = i; n < N_NODES; n += stride) {
        e0 += expf(g_scores[2 * n]     - m0);
        e1 += expf(g_scores[2 * n + 1] - m1);
    }
    #pragma unroll
    for (int o = 16; o > 0; o >>= 1) {
        e0 += __shfl_down_sync(0xffffffffu, e0, o);
        e1 += __shfl_down_sync(0xffffffffu, e1, o);
    }
    if ((threadIdx.x & 31) == 0) {
        atomicAdd(&g_ssum[0], e0);
        atomicAdd(&g_ssum[1], e1);
    }
}

// ---------------- finalize: A = attn[:,label]; y = attn^T @ h ----------------
#define CHUNK 128
__global__ __launch_bounds__(256) void finalize_kernel(
    const float* __restrict__ h, const int* __restrict__ label,
    float* __restrict__ y, float* __restrict__ A)
{
    __shared__ float sA0[CHUNK], sA1[CHUNK];
    float m0 = funmapU(g_smax[0]);
    float m1 = funmapU(g_smax[1]);
    float inv0 = 1.f / g_ssum[0];
    float inv1 = 1.f / g_ssum[1];
    int base = blockIdx.x * CHUNK;
    int t = threadIdx.x;
    int lab = label ? *label : 1;
    if (t < CHUNK) {
        int n = base + t;
        if (n < N_NODES) {
            float a0 = expf(g_scores[2 * n]     - m0) * inv0;
            float a1 = expf(g_scores[2 * n + 1] - m1) * inv1;
            sA0[t] = a0;
            sA1[t] = a1;
            A[n] = lab ? a1 : a0;
        } else {
            sA0[t] = 0.f;
            sA1[t] = 0.f;
        }
    }
    __syncthreads();
    float y0 = 0.f, y1 = 0.f;
    int nmax = N_NODES - base;
    if (nmax > CHUNK) nmax = CHUNK;
    for (int j = 0; j < nmax; j++) {
        float hv = h[(size_t)(base + j) * 256 + t];
        y0 += sA0[j] * hv;
        y1 += sA1[j] * hv;
    }
    atomicAdd(&y[t],       y0);
    atomicAdd(&y[256 + t], y1);
}

// ---------------- launch ----------------
extern "C" void kernel_launch(void* const* d_in, const int* in_sizes, int n_in,
                              void* d_out, int out_size)
{
    const float* x  = (const float*)d_in[0];
    const float* Wq = (const float*)d_in[1];
    const float* bq = (const float*)d_in[2];
    const float* Wk = (const float*)d_in[3];
    const float* bk = (const float*)d_in[4];
    const float* Wv = (const float*)d_in[5];
    const float* bv = (const float*)d_in[6];
    const float* Ws = (const float*)d_in[7];
    const float* bs = (const float*)d_in[8];
    const float* Wa = (const float*)d_in[9];
    const float* ba = (const float*)d_in[10];
    const float* Wb = (const float*)d_in[11];
    const float* bb = (const float*)d_in[12];
    const float* Wc = (const float*)d_in[13];
    const float* bc = (const float*)d_in[14];
    const int*   ei = (const int*)d_in[15];
    const int*   lab = (n_in > 16) ? (const int*)d_in[16] : nullptr;

    float* out = (float*)d_out;
    float* y = out;                       // [2, 256]
    float* A = out + 512;                 // [50000]
    float* h = out + 512 + N_NODES;       // [50000, 256]

    __half *pXh, *pW1, *pHh, *pW2, *pKVh;
    float *pZ, *pT;
    cudaGetSymbolAddress((void**)&pXh, g_Xh);
    cudaGetSymbolAddress((void**)&pW1, g_W1);
    cudaGetSymbolAddress((void**)&pZ,  g_Z);
    cudaGetSymbolAddress((void**)&pT,  g_T);
    cudaGetSymbolAddress((void**)&pW2, g_W2);
    cudaGetSymbolAddress((void**)&pHh, g_Hh);
    cudaGetSymbolAddress((void**)&pKVh, g_KVh);

    cudaFuncSetAttribute(gemm_fp16, cudaFuncAttributeMaxDynamicSharedMemorySize, GEMM_SMEM);

    convx_kernel<<<(ZROWS * 256 + 255) / 256, 256>>>(x);
    pack1_kernel<<<(1024 * 1024 + 255) / 256, 256>>>(Wq, Wk, Wv, Ws);
    pack2_kernel<<<(256 * 512 + 255) / 256, 256>>>(Wa, Wb);
    init_kernel<<<256, 256>>>(y);

    // CSR build
    count_kernel<<<(N_EDGES + 255) / 256, 256>>>(ei);
    scan_kernel<<<1, 1024>>>();
    fill_kernel<<<(N_EDGES + 255) / 256, 256>>>(ei);

    // Z = xh @ W1: cols 0..767 (q,k,v) -> fp16 g_KVh (stride 768); cols 768..1023 (s) -> fp32 g_Z
    gemm_fp16<<<dim3(1024 / BN, ZROWS / BM), 256, GEMM_SMEM>>>(
        pXh, pW1, pZ, pKVh, 1024, 768, 1024);

    // fused single-pass per-node edge softmax + gather + gelu -> h (+ fp16 copy)
    edge_fused_kernel<<<(N_NODES * 32 + 255) / 256, 256>>>(bq, bk, bv, bs, h);

    // T = hh @ W2  (all fp32 out; M=50176, N=512, K=256)
    gemm_fp16<<<dim3(512 / BN, ZROWS / BM), 256, GEMM_SMEM>>>(
        pHh, pW2, pT, nullptr, 512, 0, 256);

    scores_kernel<<<(N_NODES * 32 + 255) / 256, 256>>>(Wc, bc, ba, bb);
    sumexp_kernel<<<256, 256>>>();
    finalize_kernel<<<(N_NODES + CHUNK - 1) / CHUNK, 256>>>(h, lab, y, A);
}